// round 8
// baseline (speedup 1.0000x reference)
#include <cuda_runtime.h>
#include <cuda_bf16.h>
#include <cstdint>

// ---------------------------------------------------------------------------
// MoE forward, GB300 (sm_103a), round 1 implementation.
//   N=8192 tokens, D=1024, H=2048, E=8, TOP_K=2, HS=4096.
// Pipeline (5 launches, all default stream, graph-capturable):
//   1) gate_kernel      -> g_cw[N][8]   (fp32 exact gate + softmax + top2)
//   2) g1_swiglu (z=8)  -> g_H[e][N][H] = silu(X W1e^T + b1e) * (X W3e^T + b3e)
//   3) g2_routed        -> out = sum_e cw_e * (H_e W2e^T + b2e)  [single GEMM, K=16384,
//                          A rows pre-scaled by cw, bias-mix epilogue]
//   4) g1_swiglu (z=1)  -> g_H[N][HS] (reused scratch) shared-expert SwiGLU
//   5) g_final          -> out += Hs SW2^T + sb2
// GEMM core: mma.sync.m16n8k8 tf32 (fp32 accum), 128x128x32 CTA tiles,
// double-buffered smem with conflict-free padding (stride 36 floats).
// ---------------------------------------------------------------------------

#define NTOK   8192
#define DDIM   1024
#define HDIM   2048
#define NEXP   8
#define HSDIM  4096

// Scratch: H for all 8 experts (also reused for shared-expert hidden, 33.5M < 134M floats)
__device__ float g_H[(size_t)NEXP * NTOK * HDIM];   // 536 MB
__device__ float g_cw[NTOK * NEXP];                 // dense combine weights

// ---------------- helpers ----------------

__device__ __forceinline__ float tf32r(float x) {
    unsigned int u;
    asm("cvt.rna.tf32.f32 %0, %1;" : "=r"(u) : "f"(x));
    return __uint_as_float(u);
}

__device__ __forceinline__ void mma8(float c[4], const unsigned int a[4],
                                     unsigned int b0, unsigned int b1) {
    asm volatile(
        "mma.sync.aligned.m16n8k8.row.col.f32.tf32.tf32.f32 "
        "{%0,%1,%2,%3},{%4,%5,%6,%7},{%8,%9},{%0,%1,%2,%3};\n"
        : "+f"(c[0]), "+f"(c[1]), "+f"(c[2]), "+f"(c[3])
        : "r"(a[0]), "r"(a[1]), "r"(a[2]), "r"(a[3]), "r"(b0), "r"(b1));
}

// ---------------- 1) gate ----------------
// one warp per token; fp32 exact logits, softmax, top-2, renormalize.
__global__ void gate_kernel(const float* __restrict__ x,
                            const float* __restrict__ gw,
                            const float* __restrict__ gb) {
    const int warp = threadIdx.x >> 5, lane = threadIdx.x & 31;
    const int token = blockIdx.x * 8 + warp;
    const float* xr = x + (size_t)token * DDIM;
    float acc[NEXP];
#pragma unroll
    for (int e = 0; e < NEXP; e++) acc[e] = 0.f;
    for (int d = lane; d < DDIM; d += 32) {
        const float xv = xr[d];
#pragma unroll
        for (int e = 0; e < NEXP; e++) acc[e] += xv * gw[e * DDIM + d];
    }
#pragma unroll
    for (int e = 0; e < NEXP; e++) {
#pragma unroll
        for (int off = 16; off > 0; off >>= 1)
            acc[e] += __shfl_xor_sync(0xffffffffu, acc[e], off);
    }
    if (lane == 0) {
        float mx = -1e30f;
#pragma unroll
        for (int e = 0; e < NEXP; e++) { acc[e] += gb[e]; mx = fmaxf(mx, acc[e]); }
        float s[NEXP], sum = 0.f;
#pragma unroll
        for (int e = 0; e < NEXP; e++) { s[e] = expf(acc[e] - mx); sum += s[e]; }
        const float inv = 1.f / sum;
        int i1 = 0, i2 = 0;
        float v1 = -1.f, v2 = -1.f;
#pragma unroll
        for (int e = 0; e < NEXP; e++) {
            const float sc = s[e] * inv;
            if (sc > v1)      { v2 = v1; i2 = i1; v1 = sc; i1 = e; }
            else if (sc > v2) { v2 = sc; i2 = e; }
        }
        const float den = 1.f / (v1 + v2 + 1e-20f);
#pragma unroll
        for (int e = 0; e < NEXP; e++) g_cw[token * NEXP + e] = 0.f;
        g_cw[token * NEXP + i1] = v1 * den;
        g_cw[token * NEXP + i2] = v2 * den;
    }
}

// ---------------- 2/4) dual-GEMM SwiGLU ----------------
// CTA tile: 128(M) x 64(N), K = 1024, ktile 32, 8 warps (warp tile 64x16, dual acc).
// Writes H[z][m][n] = silu(X W1^T + b1) * (X W3^T + b3).
__global__ void __launch_bounds__(256, 1)
g1_swiglu(const float* __restrict__ X,
          const float* __restrict__ W1, const float* __restrict__ B1v,
          const float* __restrict__ W3, const float* __restrict__ B3v,
          int Nh) {
    extern __shared__ float sm[];
    float* As  = sm;                          // [2][128][36]
    float* B1s = sm + 2 * 128 * 36;           // [2][64][36]
    float* B3s = B1s + 2 * 64 * 36;           // [2][64][36]

    const int z = blockIdx.z;
    const int mBase = blockIdx.y * 128;
    const int nBase = blockIdx.x * 64;
    const float* xz  = X  + (size_t)mBase * DDIM;
    const float* w1z = W1 + (size_t)z * Nh * DDIM + (size_t)nBase * DDIM;
    const float* w3z = W3 + (size_t)z * Nh * DDIM + (size_t)nBase * DDIM;

    const int tid = threadIdx.x;
    const int row0 = tid >> 3;
    const int kc = (tid & 7) << 2;
    const int warp = tid >> 5, lane = tid & 31;
    const int g = lane >> 2, tg = lane & 3;
    const int wm = (warp & 1) << 6;     // 0 / 64
    const int wn = (warp >> 1) << 4;    // 0..48

    float c1a[4][2][4], c3a[4][2][4];
#pragma unroll
    for (int a = 0; a < 4; a++)
#pragma unroll
        for (int b = 0; b < 2; b++)
#pragma unroll
            for (int c = 0; c < 4; c++) { c1a[a][b][c] = 0.f; c3a[a][b][c] = 0.f; }

    float4 ar[4], b1r[2], b3r[2];

    auto ldg = [&](int kt) {
        const int kk = kt * 32 + kc;
#pragma unroll
        for (int i = 0; i < 4; i++)
            ar[i] = *(const float4*)(xz + (size_t)(row0 + 32 * i) * DDIM + kk);
#pragma unroll
        for (int i = 0; i < 2; i++) {
            b1r[i] = *(const float4*)(w1z + (size_t)(row0 + 32 * i) * DDIM + kk);
            b3r[i] = *(const float4*)(w3z + (size_t)(row0 + 32 * i) * DDIM + kk);
        }
    };
    auto sts = [&](int buf) {
        float* Ab = As + buf * (128 * 36);
        float* P  = B1s + buf * (64 * 36);
        float* Q  = B3s + buf * (64 * 36);
#pragma unroll
        for (int i = 0; i < 4; i++) {
            const int r = row0 + 32 * i;
            float4 a = ar[i];
            *(float4*)(Ab + r * 36 + kc) =
                make_float4(tf32r(a.x), tf32r(a.y), tf32r(a.z), tf32r(a.w));
        }
#pragma unroll
        for (int i = 0; i < 2; i++) {
            const int r = row0 + 32 * i;
            float4 p = b1r[i], q = b3r[i];
            *(float4*)(P + r * 36 + kc) =
                make_float4(tf32r(p.x), tf32r(p.y), tf32r(p.z), tf32r(p.w));
            *(float4*)(Q + r * 36 + kc) =
                make_float4(tf32r(q.x), tf32r(q.y), tf32r(q.z), tf32r(q.w));
        }
    };

    ldg(0);
    sts(0);
    __syncthreads();

    const int KT = DDIM / 32;   // 32
    for (int kt = 0; kt < KT; kt++) {
        const int cur = kt & 1;
        if (kt + 1 < KT) ldg(kt + 1);
        const float* Ab = As + cur * (128 * 36);
        const float* P  = B1s + cur * (64 * 36);
        const float* Q  = B3s + cur * (64 * 36);
#pragma unroll
        for (int ks = 0; ks < 4; ks++) {
            const int kb = ks * 8;
            unsigned int af[4][4];
#pragma unroll
            for (int mt = 0; mt < 4; mt++) {
                const float* p = Ab + (wm + mt * 16) * 36 + kb;
                af[mt][0] = __float_as_uint(p[g * 36 + tg]);
                af[mt][1] = __float_as_uint(p[(g + 8) * 36 + tg]);
                af[mt][2] = __float_as_uint(p[g * 36 + tg + 4]);
                af[mt][3] = __float_as_uint(p[(g + 8) * 36 + tg + 4]);
            }
#pragma unroll
            for (int nt = 0; nt < 2; nt++) {
                const float* pb = P + (wn + nt * 8 + g) * 36 + kb;
                const float* qb = Q + (wn + nt * 8 + g) * 36 + kb;
                const unsigned int p0 = __float_as_uint(pb[tg]);
                const unsigned int p1 = __float_as_uint(pb[tg + 4]);
                const unsigned int q0 = __float_as_uint(qb[tg]);
                const unsigned int q1 = __float_as_uint(qb[tg + 4]);
#pragma unroll
                for (int mt = 0; mt < 4; mt++) {
                    mma8(c1a[mt][nt], af[mt], p0, p1);
                    mma8(c3a[mt][nt], af[mt], q0, q1);
                }
            }
        }
        if (kt + 1 < KT) sts((kt + 1) & 1);
        __syncthreads();
    }

    // epilogue: SwiGLU + store
    const float* b1p = B1v + (size_t)z * Nh + nBase;
    const float* b3p = B3v + (size_t)z * Nh + nBase;
    float* Hz = g_H + (size_t)z * NTOK * Nh;
#pragma unroll
    for (int mt = 0; mt < 4; mt++) {
#pragma unroll
        for (int nt = 0; nt < 2; nt++) {
#pragma unroll
            for (int i = 0; i < 4; i++) {
                const int rl = wm + mt * 16 + g + ((i >> 1) << 3);
                const int cl = wn + nt * 8 + (tg << 1) + (i & 1);
                const float v1 = c1a[mt][nt][i] + __ldg(b1p + cl);
                const float v3 = c3a[mt][nt][i] + __ldg(b3p + cl);
                const float sig = 1.f / (1.f + expf(-v1));
                Hz[(size_t)(mBase + rl) * Nh + nBase + cl] = v1 * sig * v3;
            }
        }
    }
}

// ---------------- 3) routed combine GEMM ----------------
// out[m,n] = sum_{e,k} (cw[m,e]*H[e][m,k]) * W2[e][n,k] + sum_e cw[m,e]*b2[e][n]
// Single NT GEMM, K=16384, A rows scaled by cw at the smem-store stage.
__global__ void __launch_bounds__(256, 1)
g2_routed(const float* __restrict__ w2, const float* __restrict__ b2,
          float* __restrict__ out) {
    extern __shared__ float sm[];
    float* As  = sm;                    // [2][128][36]
    float* Bs  = sm + 2 * 128 * 36;     // [2][128][36]
    float* cws = sm + 4 * 128 * 36;     // [128][8]
    float* b2s = cws + 128 * 8;         // [8][128]

    const int tid = threadIdx.x;
    const int mBase = blockIdx.y * 128;
    const int nBase = blockIdx.x * 128;

    {   // stage cw slice + b2 slice
        float4 v = *(const float4*)(g_cw + mBase * NEXP + tid * 4);
        *(float4*)(cws + tid * 4) = v;
        const int e = tid >> 5, nn = (tid & 31) * 4;
        float4 w = *(const float4*)(b2 + e * DDIM + nBase + nn);
        *(float4*)(b2s + e * 128 + nn) = w;
    }

    const int row0 = tid >> 3;
    const int kc = (tid & 7) << 2;
    const int warp = tid >> 5, lane = tid & 31;
    const int g = lane >> 2, tg = lane & 3;
    const int wm = (warp & 1) << 6;
    const int wn = (warp >> 1) << 5;

    float acc[4][4][4];
#pragma unroll
    for (int a = 0; a < 4; a++)
#pragma unroll
        for (int b = 0; b < 4; b++)
#pragma unroll
            for (int c = 0; c < 4; c++) acc[a][b][c] = 0.f;

    float4 ar[4], br[4];
    int ecur = 0;

    auto ldg = [&](int kt) {
        const int kg = kt * 32;
        const int e  = kg >> 11;        // / 2048
        const int kk = (kg & 2047) + kc;
        ecur = e;
        const float* Ab = g_H + ((size_t)e * NTOK + mBase) * HDIM + kk;
        const float* Bb = w2  + ((size_t)e * DDIM + nBase) * HDIM + kk;
#pragma unroll
        for (int i = 0; i < 4; i++) {
            ar[i] = *(const float4*)(Ab + (size_t)(row0 + 32 * i) * HDIM);
            br[i] = *(const float4*)(Bb + (size_t)(row0 + 32 * i) * HDIM);
        }
    };
    auto sts = [&](int buf) {
        float* Ab = As + buf * (128 * 36);
        float* Bb = Bs + buf * (128 * 36);
#pragma unroll
        for (int i = 0; i < 4; i++) {
            const int r = row0 + 32 * i;
            const float s = cws[r * NEXP + ecur];
            float4 a = ar[i], b = br[i];
            *(float4*)(Ab + r * 36 + kc) = make_float4(
                tf32r(a.x * s), tf32r(a.y * s), tf32r(a.z * s), tf32r(a.w * s));
            *(float4*)(Bb + r * 36 + kc) = make_float4(
                tf32r(b.x), tf32r(b.y), tf32r(b.z), tf32r(b.w));
        }
    };

    ldg(0);
    __syncthreads();   // cws visible before first sts
    sts(0);
    __syncthreads();

    const int KT = (NEXP * HDIM) / 32;  // 512
    for (int kt = 0; kt < KT; kt++) {
        const int cur = kt & 1;
        if (kt + 1 < KT) ldg(kt + 1);
        const float* Ab = As + cur * (128 * 36);
        const float* Bb = Bs + cur * (128 * 36);
#pragma unroll
        for (int ks = 0; ks < 4; ks++) {
            const int kb = ks * 8;
            unsigned int af[4][4];
#pragma unroll
            for (int mt = 0; mt < 4; mt++) {
                const float* p = Ab + (wm + mt * 16) * 36 + kb;
                af[mt][0] = __float_as_uint(p[g * 36 + tg]);
                af[mt][1] = __float_as_uint(p[(g + 8) * 36 + tg]);
                af[mt][2] = __float_as_uint(p[g * 36 + tg + 4]);
                af[mt][3] = __float_as_uint(p[(g + 8) * 36 + tg + 4]);
            }
#pragma unroll
            for (int nt = 0; nt < 4; nt++) {
                const float* q = Bb + (wn + nt * 8 + g) * 36 + kb;
                const unsigned int b0 = __float_as_uint(q[tg]);
                const unsigned int b1_ = __float_as_uint(q[tg + 4]);
#pragma unroll
                for (int mt = 0; mt < 4; mt++) mma8(acc[mt][nt], af[mt], b0, b1_);
            }
        }
        if (kt + 1 < KT) sts((kt + 1) & 1);
        __syncthreads();
    }

    // epilogue: bias mix  bm = sum_e cw[m,e]*b2[e][n]; write (first writer of out)
#pragma unroll
    for (int mt = 0; mt < 4; mt++) {
#pragma unroll
        for (int nt = 0; nt < 4; nt++) {
#pragma unroll
            for (int i = 0; i < 4; i++) {
                const int rl = wm + mt * 16 + g + ((i >> 1) << 3);
                const int cl = wn + nt * 8 + (tg << 1) + (i & 1);
                float bm = 0.f;
#pragma unroll
                for (int e = 0; e < NEXP; e++) bm += cws[rl * NEXP + e] * b2s[e * 128 + cl];
                out[(size_t)(mBase + rl) * DDIM + nBase + cl] = acc[mt][nt][i] + bm;
            }
        }
    }
}

// ---------------- 5) shared-expert final GEMM (accumulate) ----------------
// out += Hs @ SW2^T + sb2 ;  Hs = g_H viewed as [8192][4096]
__global__ void __launch_bounds__(256, 1)
g_final(const float* __restrict__ B, const float* __restrict__ bias,
        float* __restrict__ out) {
    extern __shared__ float sm[];
    float* As = sm;                  // [2][128][36]
    float* Bs = sm + 2 * 128 * 36;   // [2][128][36]

    const int tid = threadIdx.x;
    const int mBase = blockIdx.y * 128;
    const int nBase = blockIdx.x * 128;

    const int row0 = tid >> 3;
    const int kc = (tid & 7) << 2;
    const int warp = tid >> 5, lane = tid & 31;
    const int g = lane >> 2, tg = lane & 3;
    const int wm = (warp & 1) << 6;
    const int wn = (warp >> 1) << 5;

    float acc[4][4][4];
#pragma unroll
    for (int a = 0; a < 4; a++)
#pragma unroll
        for (int b = 0; b < 4; b++)
#pragma unroll
            for (int c = 0; c < 4; c++) acc[a][b][c] = 0.f;

    float4 ar[4], br[4];
    const float* Abase = g_H + (size_t)mBase * HSDIM;
    const float* Bbase = B   + (size_t)nBase * HSDIM;

    auto ldg = [&](int kt) {
        const int kk = kt * 32 + kc;
#pragma unroll
        for (int i = 0; i < 4; i++) {
            ar[i] = *(const float4*)(Abase + (size_t)(row0 + 32 * i) * HSDIM + kk);
            br[i] = *(const float4*)(Bbase + (size_t)(row0 + 32 * i) * HSDIM + kk);
        }
    };
    auto sts = [&](int buf) {
        float* Ab = As + buf * (128 * 36);
        float* Bb = Bs + buf * (128 * 36);
#pragma unroll
        for (int i = 0; i < 4; i++) {
            const int r = row0 + 32 * i;
            float4 a = ar[i], b = br[i];
            *(float4*)(Ab + r * 36 + kc) =
                make_float4(tf32r(a.x), tf32r(a.y), tf32r(a.z), tf32r(a.w));
            *(float4*)(Bb + r * 36 + kc) =
                make_float4(tf32r(b.x), tf32r(b.y), tf32r(b.z), tf32r(b.w));
        }
    };

    ldg(0);
    sts(0);
    __syncthreads();

    const int KT = HSDIM / 32;  // 128
    for (int kt = 0; kt < KT; kt++) {
        const int cur = kt & 1;
        if (kt + 1 < KT) ldg(kt + 1);
        const float* Ab = As + cur * (128 * 36);
        const float* Bb = Bs + cur * (128 * 36);
#pragma unroll
        for (int ks = 0; ks < 4; ks++) {
            const int kb = ks * 8;
            unsigned int af[4][4];
#pragma unroll
            for (int mt = 0; mt < 4; mt++) {
                const float* p = Ab + (wm + mt * 16) * 36 + kb;
                af[mt][0] = __float_as_uint(p[g * 36 + tg]);
                af[mt][1] = __float_as_uint(p[(g + 8) * 36 + tg]);
                af[mt][2] = __float_as_uint(p[g * 36 + tg + 4]);
                af[mt][3] = __float_as_uint(p[(g + 8) * 36 + tg + 4]);
            }
#pragma unroll
            for (int nt = 0; nt < 4; nt++) {
                const float* q = Bb + (wn + nt * 8 + g) * 36 + kb;
                const unsigned int b0 = __float_as_uint(q[tg]);
                const unsigned int b1_ = __float_as_uint(q[tg + 4]);
#pragma unroll
                for (int mt = 0; mt < 4; mt++) mma8(acc[mt][nt], af[mt], b0, b1_);
            }
        }
        if (kt + 1 < KT) sts((kt + 1) & 1);
        __syncthreads();
    }

#pragma unroll
    for (int mt = 0; mt < 4; mt++) {
#pragma unroll
        for (int nt = 0; nt < 4; nt++) {
#pragma unroll
            for (int i = 0; i < 4; i++) {
                const int rl = wm + mt * 16 + g + ((i >> 1) << 3);
                const int cl = wn + nt * 8 + (tg << 1) + (i & 1);
                float* o = out + (size_t)(mBase + rl) * DDIM + nBase + cl;
                *o = *o + acc[mt][nt][i] + __ldg(bias + nBase + cl);
            }
        }
    }
}

// ---------------- launcher ----------------

extern "C" void kernel_launch(void* const* d_in, const int* in_sizes, int n_in,
                              void* d_out, int out_size) {
    const float* x   = (const float*)d_in[0];
    const float* gw  = (const float*)d_in[1];
    const float* gb  = (const float*)d_in[2];
    const float* w1  = (const float*)d_in[3];
    const float* b1  = (const float*)d_in[4];
    const float* w2  = (const float*)d_in[5];
    const float* b2  = (const float*)d_in[6];
    const float* w3  = (const float*)d_in[7];
    const float* b3  = (const float*)d_in[8];
    const float* sw1 = (const float*)d_in[9];
    const float* sb1 = (const float*)d_in[10];
    const float* sw2 = (const float*)d_in[11];
    const float* sb2 = (const float*)d_in[12];
    const float* sw3 = (const float*)d_in[13];
    const float* sb3 = (const float*)d_in[14];
    float* out = (float*)d_out;

    const int SMEM_G1 = (2 * 128 * 36 + 4 * 64 * 36) * 4;            // 73728 B
    const int SMEM_G2 = (4 * 128 * 36 + 128 * 8 + 8 * 128) * 4;      // 81920 B
    const int SMEM_GF = (4 * 128 * 36) * 4;                          // 73728 B

    cudaFuncSetAttribute(g1_swiglu, cudaFuncAttributeMaxDynamicSharedMemorySize, SMEM_G1);
    cudaFuncSetAttribute(g2_routed, cudaFuncAttributeMaxDynamicSharedMemorySize, SMEM_G2);
    cudaFuncSetAttribute(g_final,  cudaFuncAttributeMaxDynamicSharedMemorySize, SMEM_GF);

    // 1) gate -> g_cw
    gate_kernel<<<NTOK / 8, 256>>>(x, gw, gb);

    // 2) routed SwiGLU hidden: g_H[e][N][H]
    g1_swiglu<<<dim3(HDIM / 64, NTOK / 128, NEXP), 256, SMEM_G1>>>(
        x, w1, b1, w3, b3, HDIM);

    // 3) routed combine -> out (writes every element)
    g2_routed<<<dim3(DDIM / 128, NTOK / 128), 256, SMEM_G2>>>(w2, b2, out);

    // 4) shared-expert SwiGLU hidden (reuses g_H as [N][HS])
    g1_swiglu<<<dim3(HSDIM / 64, NTOK / 128, 1), 256, SMEM_G1>>>(
        x, sw1, sb1, sw3, sb3, HSDIM);

    // 5) shared-expert projection, accumulate into out
    g_final<<<dim3(DDIM / 128, NTOK / 128), 256, SMEM_GF>>>(sw2, sb2, out);
}

// round 9
// speedup vs baseline: 2.4424x; 2.4424x over previous
#include <cuda_runtime.h>
#include <cuda_bf16.h>
#include <cstdint>

// ---------------------------------------------------------------------------
// MoE forward, GB300 (sm_103a), round 2: SPARSE token dispatch.
//   N=8192 tokens, D=1024, H=2048, E=8, TOP_K=2, HS=4096.
// Pipeline (6 launches, default stream, graph-capturable, deterministic):
//   1) gate_kernel   -> per-token top-2 expert ids + renormalized weights
//   2) scan_dispatch -> deterministic per-expert slot permutation (prefix scan)
//   3) g1_swiglu<true>  -> H[slot] = silu(X[tok] W1e^T+b1e) * (X[tok] W3e^T+b3e)
//   4) g2_sparse        -> Y[slot] = sw[slot] * (H[slot] W2e^T + b2e)
//   5) g1_swiglu<false> -> Hs = shared-expert SwiGLU (dense, reuses g_H)
//   6) g_final          -> out[t] = Hs[t] SW2^T + sb2 + Y[pos0[t]] + Y[pos1[t]]
// GEMM core: mma.sync.m16n8k8 tf32 (fp32 accum), 128-wide CTA tiles,
// double-buffered smem, conflict-free padding (stride 36 floats).
// Total ~412 GFLOP vs 1031 GFLOP dense.
// ---------------------------------------------------------------------------

#define NTOK   8192
#define DDIM   1024
#define HDIM   2048
#define NEXP   8
#define HSDIM  4096
#define MAXSLOT (NTOK * 2 + NEXP * 128)   // 17408 (per-expert 128-padded)

// Scratch (device globals; no allocation in kernel_launch)
__device__ float g_H[(size_t)36 * 1024 * 1024];      // max(17408*2048, 8192*4096) floats
__device__ float g_Y[(size_t)MAXSLOT * DDIM];        // per-slot routed outputs
__device__ int   g_ti[NTOK * 2];                     // top-2 expert ids
__device__ float g_tw[NTOK * 2];                     // top-2 renormalized weights
__device__ int   g_pos[NTOK * 2];                    // token,k -> slot
__device__ int   g_gather[MAXSLOT];                  // slot -> token
__device__ float g_sw[MAXSLOT];                      // slot -> combine weight
__device__ int   g_cnt[NEXP];                        // tokens per expert
__device__ int   g_base[NEXP];                       // padded slot base per expert

// ---------------- helpers ----------------

__device__ __forceinline__ float tf32r(float x) {
    unsigned int u;
    asm("cvt.rna.tf32.f32 %0, %1;" : "=r"(u) : "f"(x));
    return __uint_as_float(u);
}

__device__ __forceinline__ void mma8(float c[4], const unsigned int a[4],
                                     unsigned int b0, unsigned int b1) {
    asm volatile(
        "mma.sync.aligned.m16n8k8.row.col.f32.tf32.tf32.f32 "
        "{%0,%1,%2,%3},{%4,%5,%6,%7},{%8,%9},{%0,%1,%2,%3};\n"
        : "+f"(c[0]), "+f"(c[1]), "+f"(c[2]), "+f"(c[3])
        : "r"(a[0]), "r"(a[1]), "r"(a[2]), "r"(a[3]), "r"(b0), "r"(b1));
}

// ---------------- 1) gate ----------------
__global__ void gate_kernel(const float* __restrict__ x,
                            const float* __restrict__ gw,
                            const float* __restrict__ gb) {
    const int warp = threadIdx.x >> 5, lane = threadIdx.x & 31;
    const int token = blockIdx.x * 8 + warp;
    const float* xr = x + (size_t)token * DDIM;
    float acc[NEXP];
#pragma unroll
    for (int e = 0; e < NEXP; e++) acc[e] = 0.f;
    for (int d = lane; d < DDIM; d += 32) {
        const float xv = xr[d];
#pragma unroll
        for (int e = 0; e < NEXP; e++) acc[e] += xv * gw[e * DDIM + d];
    }
#pragma unroll
    for (int e = 0; e < NEXP; e++) {
#pragma unroll
        for (int off = 16; off > 0; off >>= 1)
            acc[e] += __shfl_xor_sync(0xffffffffu, acc[e], off);
    }
    if (lane == 0) {
        float mx = -1e30f;
#pragma unroll
        for (int e = 0; e < NEXP; e++) { acc[e] += gb[e]; mx = fmaxf(mx, acc[e]); }
        float s[NEXP], sum = 0.f;
#pragma unroll
        for (int e = 0; e < NEXP; e++) { s[e] = expf(acc[e] - mx); sum += s[e]; }
        const float inv = 1.f / sum;
        int i1 = 0, i2 = 0;
        float v1 = -1.f, v2 = -1.f;
#pragma unroll
        for (int e = 0; e < NEXP; e++) {
            const float sc = s[e] * inv;
            if (sc > v1)      { v2 = v1; i2 = i1; v1 = sc; i1 = e; }
            else if (sc > v2) { v2 = sc; i2 = e; }
        }
        const float den = 1.f / (v1 + v2 + 1e-20f);
        g_ti[token * 2]     = i1;
        g_ti[token * 2 + 1] = i2;
        g_tw[token * 2]     = v1 * den;
        g_tw[token * 2 + 1] = v2 * den;
    }
}

// ---------------- 2) deterministic dispatch (prefix scan) ----------------
// CTA e scans the "routed-to-e" indicator over all tokens in token order.
__global__ void scan_dispatch() {
    const int e = blockIdx.x;
    const int tid = threadIdx.x;          // 256 threads, 32 tokens each
    __shared__ int s_scan[256];
    __shared__ int s_cnt[NEXP];
    if (tid < NEXP) s_cnt[tid] = 0;
    __syncthreads();

    int ca[NEXP];
#pragma unroll
    for (int k = 0; k < NEXP; k++) ca[k] = 0;
    int my = 0;
    const int t0 = tid * 32;
    for (int i = 0; i < 32; i++) {
        const int t = t0 + i;
        const int e0 = g_ti[2 * t], e1 = g_ti[2 * t + 1];
        ca[e0]++; ca[e1]++;
        if (e0 == e || e1 == e) my++;
    }
#pragma unroll
    for (int k = 0; k < NEXP; k++) atomicAdd(&s_cnt[k], ca[k]);
    s_scan[tid] = my;
    __syncthreads();
    // inclusive Hillis-Steele scan
    for (int off = 1; off < 256; off <<= 1) {
        int v = (tid >= off) ? s_scan[tid - off] : 0;
        __syncthreads();
        s_scan[tid] += v;
        __syncthreads();
    }

    int base = 0;
#pragma unroll
    for (int k = 0; k < NEXP; k++)
        if (k < e) base += ((s_cnt[k] + 127) >> 7) << 7;

    int pos = base + s_scan[tid] - my;    // exclusive prefix
    for (int i = 0; i < 32; i++) {
        const int t = t0 + i;
#pragma unroll
        for (int k = 0; k < 2; k++) {
            if (g_ti[2 * t + k] == e) {
                g_pos[2 * t + k] = pos;
                g_gather[pos] = t;
                g_sw[pos] = g_tw[2 * t + k];
                pos++;
            }
        }
    }
    // zero the padding tail of this expert's slot range
    const int cnt = s_cnt[e];
    const int padEnd = ((cnt + 127) >> 7) << 7;
    for (int p = cnt + tid; p < padEnd; p += 256) {
        g_gather[base + p] = 0;
        g_sw[base + p] = 0.f;
    }
    if (tid == 0) { g_cnt[e] = cnt; g_base[e] = base; }
}

// ---------------- 3/5) dual-GEMM SwiGLU (sparse gather or dense) ----------------
// CTA tile 128(M) x 64(N), K=1024, ktile 32, 8 warps.
template <bool SPARSE>
__global__ void __launch_bounds__(256, 1)
g1_swiglu(const float* __restrict__ X,
          const float* __restrict__ W1, const float* __restrict__ B1v,
          const float* __restrict__ W3, const float* __restrict__ B3v,
          int Nh) {
    extern __shared__ float sm[];
    float* As  = sm;                          // [2][128][36]
    float* B1s = sm + 2 * 128 * 36;           // [2][64][36]
    float* B3s = B1s + 2 * 64 * 36;           // [2][64][36]

    const int z = blockIdx.z;
    const int mBase = blockIdx.y * 128;
    int rowOff = mBase;
    if (SPARSE) {
        if (mBase >= g_cnt[z]) return;        // early-exit empty tiles
        rowOff = g_base[z] + mBase;
    }
    const int nBase = blockIdx.x * 64;
    const float* w1z = W1 + (size_t)z * Nh * DDIM + (size_t)nBase * DDIM;
    const float* w3z = W3 + (size_t)z * Nh * DDIM + (size_t)nBase * DDIM;

    const int tid = threadIdx.x;
    const int row0 = tid >> 3;
    const int kc = (tid & 7) << 2;
    const int warp = tid >> 5, lane = tid & 31;
    const int g = lane >> 2, tg = lane & 3;
    const int wm = (warp & 1) << 6;
    const int wn = (warp >> 1) << 4;

    int tok[4];
#pragma unroll
    for (int i = 0; i < 4; i++) {
        const int r = row0 + 32 * i;
        tok[i] = SPARSE ? g_gather[rowOff + r] : (mBase + r);
    }

    float c1a[4][2][4], c3a[4][2][4];
#pragma unroll
    for (int a = 0; a < 4; a++)
#pragma unroll
        for (int b = 0; b < 2; b++)
#pragma unroll
            for (int c = 0; c < 4; c++) { c1a[a][b][c] = 0.f; c3a[a][b][c] = 0.f; }

    float4 ar[4], b1r[2], b3r[2];

    auto ldg = [&](int kt) {
        const int kk = kt * 32 + kc;
#pragma unroll
        for (int i = 0; i < 4; i++)
            ar[i] = *(const float4*)(X + (size_t)tok[i] * DDIM + kk);
#pragma unroll
        for (int i = 0; i < 2; i++) {
            b1r[i] = *(const float4*)(w1z + (size_t)(row0 + 32 * i) * DDIM + kk);
            b3r[i] = *(const float4*)(w3z + (size_t)(row0 + 32 * i) * DDIM + kk);
        }
    };
    auto sts = [&](int buf) {
        float* Ab = As + buf * (128 * 36);
        float* P  = B1s + buf * (64 * 36);
        float* Q  = B3s + buf * (64 * 36);
#pragma unroll
        for (int i = 0; i < 4; i++) {
            const int r = row0 + 32 * i;
            float4 a = ar[i];
            *(float4*)(Ab + r * 36 + kc) =
                make_float4(tf32r(a.x), tf32r(a.y), tf32r(a.z), tf32r(a.w));
        }
#pragma unroll
        for (int i = 0; i < 2; i++) {
            const int r = row0 + 32 * i;
            float4 p = b1r[i], q = b3r[i];
            *(float4*)(P + r * 36 + kc) =
                make_float4(tf32r(p.x), tf32r(p.y), tf32r(p.z), tf32r(p.w));
            *(float4*)(Q + r * 36 + kc) =
                make_float4(tf32r(q.x), tf32r(q.y), tf32r(q.z), tf32r(q.w));
        }
    };

    ldg(0);
    sts(0);
    __syncthreads();

    const int KT = DDIM / 32;
    for (int kt = 0; kt < KT; kt++) {
        const int cur = kt & 1;
        if (kt + 1 < KT) ldg(kt + 1);
        const float* Ab = As + cur * (128 * 36);
        const float* P  = B1s + cur * (64 * 36);
        const float* Q  = B3s + cur * (64 * 36);
#pragma unroll
        for (int ks = 0; ks < 4; ks++) {
            const int kb = ks * 8;
            unsigned int af[4][4];
#pragma unroll
            for (int mt = 0; mt < 4; mt++) {
                const float* p = Ab + (wm + mt * 16) * 36 + kb;
                af[mt][0] = __float_as_uint(p[g * 36 + tg]);
                af[mt][1] = __float_as_uint(p[(g + 8) * 36 + tg]);
                af[mt][2] = __float_as_uint(p[g * 36 + tg + 4]);
                af[mt][3] = __float_as_uint(p[(g + 8) * 36 + tg + 4]);
            }
#pragma unroll
            for (int nt = 0; nt < 2; nt++) {
                const float* pb = P + (wn + nt * 8 + g) * 36 + kb;
                const float* qb = Q + (wn + nt * 8 + g) * 36 + kb;
                const unsigned int p0 = __float_as_uint(pb[tg]);
                const unsigned int p1 = __float_as_uint(pb[tg + 4]);
                const unsigned int q0 = __float_as_uint(qb[tg]);
                const unsigned int q1 = __float_as_uint(qb[tg + 4]);
#pragma unroll
                for (int mt = 0; mt < 4; mt++) {
                    mma8(c1a[mt][nt], af[mt], p0, p1);
                    mma8(c3a[mt][nt], af[mt], q0, q1);
                }
            }
        }
        if (kt + 1 < KT) sts((kt + 1) & 1);
        __syncthreads();
    }

    const float* b1p = B1v + (size_t)z * Nh + nBase;
    const float* b3p = B3v + (size_t)z * Nh + nBase;
#pragma unroll
    for (int mt = 0; mt < 4; mt++) {
#pragma unroll
        for (int nt = 0; nt < 2; nt++) {
#pragma unroll
            for (int i = 0; i < 4; i++) {
                const int rl = wm + mt * 16 + g + ((i >> 1) << 3);
                const int cl = wn + nt * 8 + (tg << 1) + (i & 1);
                const float v1 = c1a[mt][nt][i] + __ldg(b1p + cl);
                const float v3 = c3a[mt][nt][i] + __ldg(b3p + cl);
                const float sig = 1.f / (1.f + expf(-v1));
                g_H[(size_t)(rowOff + rl) * Nh + nBase + cl] = v1 * sig * v3;
            }
        }
    }
}

// ---------------- 4) sparse per-expert down-projection ----------------
// Y[slot, n] = sw[slot] * (H[slot] @ W2[e]^T + b2[e])[n]
__global__ void __launch_bounds__(256, 1)
g2_sparse(const float* __restrict__ w2, const float* __restrict__ b2) {
    extern __shared__ float sm[];
    float* As = sm;                  // [2][128][36]
    float* Bs = sm + 2 * 128 * 36;   // [2][128][36]

    const int e = blockIdx.z;
    const int mBase = blockIdx.y * 128;
    if (mBase >= g_cnt[e]) return;
    const int slot0 = g_base[e] + mBase;
    const int nBase = blockIdx.x * 128;

    const int tid = threadIdx.x;
    const int row0 = tid >> 3;
    const int kc = (tid & 7) << 2;
    const int warp = tid >> 5, lane = tid & 31;
    const int g = lane >> 2, tg = lane & 3;
    const int wm = (warp & 1) << 6;
    const int wn = (warp >> 1) << 5;

    float acc[4][4][4];
#pragma unroll
    for (int a = 0; a < 4; a++)
#pragma unroll
        for (int b = 0; b < 4; b++)
#pragma unroll
            for (int c = 0; c < 4; c++) acc[a][b][c] = 0.f;

    float4 ar[4], br[4];
    const float* Abase = g_H + (size_t)slot0 * HDIM;
    const float* Bbase = w2 + ((size_t)e * DDIM + nBase) * HDIM;

    auto ldg = [&](int kt) {
        const int kk = kt * 32 + kc;
#pragma unroll
        for (int i = 0; i < 4; i++) {
            ar[i] = *(const float4*)(Abase + (size_t)(row0 + 32 * i) * HDIM + kk);
            br[i] = *(const float4*)(Bbase + (size_t)(row0 + 32 * i) * HDIM + kk);
        }
    };
    auto sts = [&](int buf) {
        float* Ab = As + buf * (128 * 36);
        float* Bb = Bs + buf * (128 * 36);
#pragma unroll
        for (int i = 0; i < 4; i++) {
            const int r = row0 + 32 * i;
            float4 a = ar[i], b = br[i];
            *(float4*)(Ab + r * 36 + kc) =
                make_float4(tf32r(a.x), tf32r(a.y), tf32r(a.z), tf32r(a.w));
            *(float4*)(Bb + r * 36 + kc) =
                make_float4(tf32r(b.x), tf32r(b.y), tf32r(b.z), tf32r(b.w));
        }
    };

    ldg(0);
    sts(0);
    __syncthreads();

    const int KT = HDIM / 32;   // 64
    for (int kt = 0; kt < KT; kt++) {
        const int cur = kt & 1;
        if (kt + 1 < KT) ldg(kt + 1);
        const float* Ab = As + cur * (128 * 36);
        const float* Bb = Bs + cur * (128 * 36);
#pragma unroll
        for (int ks = 0; ks < 4; ks++) {
            const int kb = ks * 8;
            unsigned int af[4][4];
#pragma unroll
            for (int mt = 0; mt < 4; mt++) {
                const float* p = Ab + (wm + mt * 16) * 36 + kb;
                af[mt][0] = __float_as_uint(p[g * 36 + tg]);
                af[mt][1] = __float_as_uint(p[(g + 8) * 36 + tg]);
                af[mt][2] = __float_as_uint(p[g * 36 + tg + 4]);
                af[mt][3] = __float_as_uint(p[(g + 8) * 36 + tg + 4]);
            }
#pragma unroll
            for (int nt = 0; nt < 4; nt++) {
                const float* q = Bb + (wn + nt * 8 + g) * 36 + kb;
                const unsigned int b0 = __float_as_uint(q[tg]);
                const unsigned int b1_ = __float_as_uint(q[tg + 4]);
#pragma unroll
                for (int mt = 0; mt < 4; mt++) mma8(acc[mt][nt], af[mt], b0, b1_);
            }
        }
        if (kt + 1 < KT) sts((kt + 1) & 1);
        __syncthreads();
    }

    const float* b2p = b2 + (size_t)e * DDIM + nBase;
#pragma unroll
    for (int mt = 0; mt < 4; mt++) {
#pragma unroll
        for (int i = 0; i < 4; i++) {
            const int rl = wm + mt * 16 + g + ((i >> 1) << 3);
            const int slot = slot0 + rl;
            const float swv = __ldg(g_sw + slot);
#pragma unroll
            for (int nt = 0; nt < 4; nt++) {
                const int cl = wn + nt * 8 + (tg << 1) + (i & 1);
                g_Y[(size_t)slot * DDIM + nBase + cl] =
                    swv * (acc[mt][nt][i] + __ldg(b2p + cl));
            }
        }
    }
}

// ---------------- 6) shared-expert projection + routed combine ----------------
// out[t] = Hs[t] @ SW2^T + sb2 + Y[pos0[t]] + Y[pos1[t]]
__global__ void __launch_bounds__(256, 1)
g_final(const float* __restrict__ B, const float* __restrict__ bias,
        float* __restrict__ out) {
    extern __shared__ float sm[];
    float* As = sm;                  // [2][128][36]
    float* Bs = sm + 2 * 128 * 36;   // [2][128][36]

    const int tid = threadIdx.x;
    const int mBase = blockIdx.y * 128;
    const int nBase = blockIdx.x * 128;

    const int row0 = tid >> 3;
    const int kc = (tid & 7) << 2;
    const int warp = tid >> 5, lane = tid & 31;
    const int g = lane >> 2, tg = lane & 3;
    const int wm = (warp & 1) << 6;
    const int wn = (warp >> 1) << 5;

    float acc[4][4][4];
#pragma unroll
    for (int a = 0; a < 4; a++)
#pragma unroll
        for (int b = 0; b < 4; b++)
#pragma unroll
            for (int c = 0; c < 4; c++) acc[a][b][c] = 0.f;

    float4 ar[4], br[4];
    const float* Abase = g_H + (size_t)mBase * HSDIM;
    const float* Bbase = B   + (size_t)nBase * HSDIM;

    auto ldg = [&](int kt) {
        const int kk = kt * 32 + kc;
#pragma unroll
        for (int i = 0; i < 4; i++) {
            ar[i] = *(const float4*)(Abase + (size_t)(row0 + 32 * i) * HSDIM + kk);
            br[i] = *(const float4*)(Bbase + (size_t)(row0 + 32 * i) * HSDIM + kk);
        }
    };
    auto sts = [&](int buf) {
        float* Ab = As + buf * (128 * 36);
        float* Bb = Bs + buf * (128 * 36);
#pragma unroll
        for (int i = 0; i < 4; i++) {
            const int r = row0 + 32 * i;
            float4 a = ar[i], b = br[i];
            *(float4*)(Ab + r * 36 + kc) =
                make_float4(tf32r(a.x), tf32r(a.y), tf32r(a.z), tf32r(a.w));
            *(float4*)(Bb + r * 36 + kc) =
                make_float4(tf32r(b.x), tf32r(b.y), tf32r(b.z), tf32r(b.w));
        }
    };

    ldg(0);
    sts(0);
    __syncthreads();

    const int KT = HSDIM / 32;  // 128
    for (int kt = 0; kt < KT; kt++) {
        const int cur = kt & 1;
        if (kt + 1 < KT) ldg(kt + 1);
        const float* Ab = As + cur * (128 * 36);
        const float* Bb = Bs + cur * (128 * 36);
#pragma unroll
        for (int ks = 0; ks < 4; ks++) {
            const int kb = ks * 8;
            unsigned int af[4][4];
#pragma unroll
            for (int mt = 0; mt < 4; mt++) {
                const float* p = Ab + (wm + mt * 16) * 36 + kb;
                af[mt][0] = __float_as_uint(p[g * 36 + tg]);
                af[mt][1] = __float_as_uint(p[(g + 8) * 36 + tg]);
                af[mt][2] = __float_as_uint(p[g * 36 + tg + 4]);
                af[mt][3] = __float_as_uint(p[(g + 8) * 36 + tg + 4]);
            }
#pragma unroll
            for (int nt = 0; nt < 4; nt++) {
                const float* q = Bb + (wn + nt * 8 + g) * 36 + kb;
                const unsigned int b0 = __float_as_uint(q[tg]);
                const unsigned int b1_ = __float_as_uint(q[tg + 4]);
#pragma unroll
                for (int mt = 0; mt < 4; mt++) mma8(acc[mt][nt], af[mt], b0, b1_);
            }
        }
        if (kt + 1 < KT) sts((kt + 1) & 1);
        __syncthreads();
    }

#pragma unroll
    for (int mt = 0; mt < 4; mt++) {
#pragma unroll
        for (int i = 0; i < 4; i++) {
            const int rl = wm + mt * 16 + g + ((i >> 1) << 3);
            const int t = mBase + rl;
            const int p0 = __ldg(g_pos + 2 * t);
            const int p1 = __ldg(g_pos + 2 * t + 1);
            const float* y0 = g_Y + (size_t)p0 * DDIM + nBase;
            const float* y1 = g_Y + (size_t)p1 * DDIM + nBase;
#pragma unroll
            for (int nt = 0; nt < 4; nt++) {
                const int cl = wn + nt * 8 + (tg << 1) + (i & 1);
                out[(size_t)t * DDIM + nBase + cl] =
                    acc[mt][nt][i] + __ldg(bias + nBase + cl) +
                    __ldg(y0 + cl) + __ldg(y1 + cl);
            }
        }
    }
}

// ---------------- launcher ----------------

extern "C" void kernel_launch(void* const* d_in, const int* in_sizes, int n_in,
                              void* d_out, int out_size) {
    const float* x   = (const float*)d_in[0];
    const float* gw  = (const float*)d_in[1];
    const float* gb  = (const float*)d_in[2];
    const float* w1  = (const float*)d_in[3];
    const float* b1  = (const float*)d_in[4];
    const float* w2  = (const float*)d_in[5];
    const float* b2  = (const float*)d_in[6];
    const float* w3  = (const float*)d_in[7];
    const float* b3  = (const float*)d_in[8];
    const float* sw1 = (const float*)d_in[9];
    const float* sb1 = (const float*)d_in[10];
    const float* sw2 = (const float*)d_in[11];
    const float* sb2 = (const float*)d_in[12];
    const float* sw3 = (const float*)d_in[13];
    const float* sb3 = (const float*)d_in[14];
    float* out = (float*)d_out;

    const int SMEM_G1 = (2 * 128 * 36 + 4 * 64 * 36) * 4;   // 73728 B
    const int SMEM_GG = (4 * 128 * 36) * 4;                 // 73728 B

    cudaFuncSetAttribute(g1_swiglu<true>,
                         cudaFuncAttributeMaxDynamicSharedMemorySize, SMEM_G1);
    cudaFuncSetAttribute(g1_swiglu<false>,
                         cudaFuncAttributeMaxDynamicSharedMemorySize, SMEM_G1);
    cudaFuncSetAttribute(g2_sparse,
                         cudaFuncAttributeMaxDynamicSharedMemorySize, SMEM_GG);
    cudaFuncSetAttribute(g_final,
                         cudaFuncAttributeMaxDynamicSharedMemorySize, SMEM_GG);

    // 1) gate -> top-2 ids/weights
    gate_kernel<<<NTOK / 8, 256>>>(x, gw, gb);

    // 2) deterministic dispatch tables
    scan_dispatch<<<NEXP, 256>>>();

    // 3) sparse routed SwiGLU (early-exit tiles beyond each expert's count)
    g1_swiglu<true><<<dim3(HDIM / 64, 64, NEXP), 256, SMEM_G1>>>(
        x, w1, b1, w3, b3, HDIM);

    // 4) sparse routed down-projection -> g_Y
    g2_sparse<<<dim3(DDIM / 128, 64, NEXP), 256, SMEM_GG>>>(w2, b2);

    // 5) shared-expert SwiGLU hidden (dense, reuses g_H as [N][HS])
    g1_swiglu<false><<<dim3(HSDIM / 64, NTOK / 128, 1), 256, SMEM_G1>>>(
        x, sw1, sb1, sw3, sb3, HSDIM);

    // 6) shared projection + routed combine -> out (single write)
    g_final<<<dim3(DDIM / 128, NTOK / 128), 256, SMEM_GG>>>(sw2, sb2, out);
}

// round 10
// speedup vs baseline: 2.4436x; 1.0005x over previous
#include <cuda_runtime.h>
#include <cuda_bf16.h>
#include <cstdint>

// ---------------------------------------------------------------------------
// MoE forward, GB300 (sm_103a), round 2: SPARSE token dispatch.
//   N=8192 tokens, D=1024, H=2048, E=8, TOP_K=2, HS=4096.
// Pipeline (6 launches, default stream, graph-capturable, deterministic):
//   1) gate_kernel   -> per-token top-2 expert ids + renormalized weights
//   2) scan_dispatch -> deterministic per-expert slot permutation (prefix scan)
//   3) g1_swiglu<true>  -> H[slot] = silu(X[tok] W1e^T+b1e) * (X[tok] W3e^T+b3e)
//   4) g2_sparse        -> Y[slot] = sw[slot] * (H[slot] W2e^T + b2e)
//   5) g1_swiglu<false> -> Hs = shared-expert SwiGLU (dense, reuses g_H)
//   6) g_final          -> out[t] = Hs[t] SW2^T + sb2 + Y[pos0[t]] + Y[pos1[t]]
// GEMM core: mma.sync.m16n8k8 tf32 (fp32 accum), 128-wide CTA tiles,
// double-buffered smem, conflict-free padding (stride 36 floats).
// Total ~412 GFLOP vs 1031 GFLOP dense.
// ---------------------------------------------------------------------------

#define NTOK   8192
#define DDIM   1024
#define HDIM   2048
#define NEXP   8
#define HSDIM  4096
#define MAXSLOT (NTOK * 2 + NEXP * 128)   // 17408 (per-expert 128-padded)

// Scratch (device globals; no allocation in kernel_launch)
__device__ float g_H[(size_t)36 * 1024 * 1024];      // max(17408*2048, 8192*4096) floats
__device__ float g_Y[(size_t)MAXSLOT * DDIM];        // per-slot routed outputs
__device__ int   g_ti[NTOK * 2];                     // top-2 expert ids
__device__ float g_tw[NTOK * 2];                     // top-2 renormalized weights
__device__ int   g_pos[NTOK * 2];                    // token,k -> slot
__device__ int   g_gather[MAXSLOT];                  // slot -> token
__device__ float g_sw[MAXSLOT];                      // slot -> combine weight
__device__ int   g_cnt[NEXP];                        // tokens per expert
__device__ int   g_base[NEXP];                       // padded slot base per expert

// ---------------- helpers ----------------

__device__ __forceinline__ float tf32r(float x) {
    unsigned int u;
    asm("cvt.rna.tf32.f32 %0, %1;" : "=r"(u) : "f"(x));
    return __uint_as_float(u);
}

__device__ __forceinline__ void mma8(float c[4], const unsigned int a[4],
                                     unsigned int b0, unsigned int b1) {
    asm volatile(
        "mma.sync.aligned.m16n8k8.row.col.f32.tf32.tf32.f32 "
        "{%0,%1,%2,%3},{%4,%5,%6,%7},{%8,%9},{%0,%1,%2,%3};\n"
        : "+f"(c[0]), "+f"(c[1]), "+f"(c[2]), "+f"(c[3])
        : "r"(a[0]), "r"(a[1]), "r"(a[2]), "r"(a[3]), "r"(b0), "r"(b1));
}

// ---------------- 1) gate ----------------
__global__ void gate_kernel(const float* __restrict__ x,
                            const float* __restrict__ gw,
                            const float* __restrict__ gb) {
    const int warp = threadIdx.x >> 5, lane = threadIdx.x & 31;
    const int token = blockIdx.x * 8 + warp;
    const float* xr = x + (size_t)token * DDIM;
    float acc[NEXP];
#pragma unroll
    for (int e = 0; e < NEXP; e++) acc[e] = 0.f;
    for (int d = lane; d < DDIM; d += 32) {
        const float xv = xr[d];
#pragma unroll
        for (int e = 0; e < NEXP; e++) acc[e] += xv * gw[e * DDIM + d];
    }
#pragma unroll
    for (int e = 0; e < NEXP; e++) {
#pragma unroll
        for (int off = 16; off > 0; off >>= 1)
            acc[e] += __shfl_xor_sync(0xffffffffu, acc[e], off);
    }
    if (lane == 0) {
        float mx = -1e30f;
#pragma unroll
        for (int e = 0; e < NEXP; e++) { acc[e] += gb[e]; mx = fmaxf(mx, acc[e]); }
        float s[NEXP], sum = 0.f;
#pragma unroll
        for (int e = 0; e < NEXP; e++) { s[e] = expf(acc[e] - mx); sum += s[e]; }
        const float inv = 1.f / sum;
        int i1 = 0, i2 = 0;
        float v1 = -1.f, v2 = -1.f;
#pragma unroll
        for (int e = 0; e < NEXP; e++) {
            const float sc = s[e] * inv;
            if (sc > v1)      { v2 = v1; i2 = i1; v1 = sc; i1 = e; }
            else if (sc > v2) { v2 = sc; i2 = e; }
        }
        const float den = 1.f / (v1 + v2 + 1e-20f);
        g_ti[token * 2]     = i1;
        g_ti[token * 2 + 1] = i2;
        g_tw[token * 2]     = v1 * den;
        g_tw[token * 2 + 1] = v2 * den;
    }
}

// ---------------- 2) deterministic dispatch (prefix scan) ----------------
// CTA e scans the "routed-to-e" indicator over all tokens in token order.
__global__ void scan_dispatch() {
    const int e = blockIdx.x;
    const int tid = threadIdx.x;          // 256 threads, 32 tokens each
    __shared__ int s_scan[256];
    __shared__ int s_cnt[NEXP];
    if (tid < NEXP) s_cnt[tid] = 0;
    __syncthreads();

    int ca[NEXP];
#pragma unroll
    for (int k = 0; k < NEXP; k++) ca[k] = 0;
    int my = 0;
    const int t0 = tid * 32;
    for (int i = 0; i < 32; i++) {
        const int t = t0 + i;
        const int e0 = g_ti[2 * t], e1 = g_ti[2 * t + 1];
        ca[e0]++; ca[e1]++;
        if (e0 == e || e1 == e) my++;
    }
#pragma unroll
    for (int k = 0; k < NEXP; k++) atomicAdd(&s_cnt[k], ca[k]);
    s_scan[tid] = my;
    __syncthreads();
    // inclusive Hillis-Steele scan
    for (int off = 1; off < 256; off <<= 1) {
        int v = (tid >= off) ? s_scan[tid - off] : 0;
        __syncthreads();
        s_scan[tid] += v;
        __syncthreads();
    }

    int base = 0;
#pragma unroll
    for (int k = 0; k < NEXP; k++)
        if (k < e) base += ((s_cnt[k] + 127) >> 7) << 7;

    int pos = base + s_scan[tid] - my;    // exclusive prefix
    for (int i = 0; i < 32; i++) {
        const int t = t0 + i;
#pragma unroll
        for (int k = 0; k < 2; k++) {
            if (g_ti[2 * t + k] == e) {
                g_pos[2 * t + k] = pos;
                g_gather[pos] = t;
                g_sw[pos] = g_tw[2 * t + k];
                pos++;
            }
        }
    }
    // zero the padding tail of this expert's slot range
    const int cnt = s_cnt[e];
    const int padEnd = ((cnt + 127) >> 7) << 7;
    for (int p = cnt + tid; p < padEnd; p += 256) {
        g_gather[base + p] = 0;
        g_sw[base + p] = 0.f;
    }
    if (tid == 0) { g_cnt[e] = cnt; g_base[e] = base; }
}

// ---------------- 3/5) dual-GEMM SwiGLU (sparse gather or dense) ----------------
// CTA tile 128(M) x 64(N), K=1024, ktile 32, 8 warps.
template <bool SPARSE>
__global__ void __launch_bounds__(256, 1)
g1_swiglu(const float* __restrict__ X,
          const float* __restrict__ W1, const float* __restrict__ B1v,
          const float* __restrict__ W3, const float* __restrict__ B3v,
          int Nh) {
    extern __shared__ float sm[];
    float* As  = sm;                          // [2][128][36]
    float* B1s = sm + 2 * 128 * 36;           // [2][64][36]
    float* B3s = B1s + 2 * 64 * 36;           // [2][64][36]

    const int z = blockIdx.z;
    const int mBase = blockIdx.y * 128;
    int rowOff = mBase;
    if (SPARSE) {
        if (mBase >= g_cnt[z]) return;        // early-exit empty tiles
        rowOff = g_base[z] + mBase;
    }
    const int nBase = blockIdx.x * 64;
    const float* w1z = W1 + (size_t)z * Nh * DDIM + (size_t)nBase * DDIM;
    const float* w3z = W3 + (size_t)z * Nh * DDIM + (size_t)nBase * DDIM;

    const int tid = threadIdx.x;
    const int row0 = tid >> 3;
    const int kc = (tid & 7) << 2;
    const int warp = tid >> 5, lane = tid & 31;
    const int g = lane >> 2, tg = lane & 3;
    const int wm = (warp & 1) << 6;
    const int wn = (warp >> 1) << 4;

    int tok[4];
#pragma unroll
    for (int i = 0; i < 4; i++) {
        const int r = row0 + 32 * i;
        tok[i] = SPARSE ? g_gather[rowOff + r] : (mBase + r);
    }

    float c1a[4][2][4], c3a[4][2][4];
#pragma unroll
    for (int a = 0; a < 4; a++)
#pragma unroll
        for (int b = 0; b < 2; b++)
#pragma unroll
            for (int c = 0; c < 4; c++) { c1a[a][b][c] = 0.f; c3a[a][b][c] = 0.f; }

    float4 ar[4], b1r[2], b3r[2];

    auto ldg = [&](int kt) {
        const int kk = kt * 32 + kc;
#pragma unroll
        for (int i = 0; i < 4; i++)
            ar[i] = *(const float4*)(X + (size_t)tok[i] * DDIM + kk);
#pragma unroll
        for (int i = 0; i < 2; i++) {
            b1r[i] = *(const float4*)(w1z + (size_t)(row0 + 32 * i) * DDIM + kk);
            b3r[i] = *(const float4*)(w3z + (size_t)(row0 + 32 * i) * DDIM + kk);
        }
    };
    auto sts = [&](int buf) {
        float* Ab = As + buf * (128 * 36);
        float* P  = B1s + buf * (64 * 36);
        float* Q  = B3s + buf * (64 * 36);
#pragma unroll
        for (int i = 0; i < 4; i++) {
            const int r = row0 + 32 * i;
            float4 a = ar[i];
            *(float4*)(Ab + r * 36 + kc) =
                make_float4(tf32r(a.x), tf32r(a.y), tf32r(a.z), tf32r(a.w));
        }
#pragma unroll
        for (int i = 0; i < 2; i++) {
            const int r = row0 + 32 * i;
            float4 p = b1r[i], q = b3r[i];
            *(float4*)(P + r * 36 + kc) =
                make_float4(tf32r(p.x), tf32r(p.y), tf32r(p.z), tf32r(p.w));
            *(float4*)(Q + r * 36 + kc) =
                make_float4(tf32r(q.x), tf32r(q.y), tf32r(q.z), tf32r(q.w));
        }
    };

    ldg(0);
    sts(0);
    __syncthreads();

    const int KT = DDIM / 32;
    for (int kt = 0; kt < KT; kt++) {
        const int cur = kt & 1;
        if (kt + 1 < KT) ldg(kt + 1);
        const float* Ab = As + cur * (128 * 36);
        const float* P  = B1s + cur * (64 * 36);
        const float* Q  = B3s + cur * (64 * 36);
#pragma unroll
        for (int ks = 0; ks < 4; ks++) {
            const int kb = ks * 8;
            unsigned int af[4][4];
#pragma unroll
            for (int mt = 0; mt < 4; mt++) {
                const float* p = Ab + (wm + mt * 16) * 36 + kb;
                af[mt][0] = __float_as_uint(p[g * 36 + tg]);
                af[mt][1] = __float_as_uint(p[(g + 8) * 36 + tg]);
                af[mt][2] = __float_as_uint(p[g * 36 + tg + 4]);
                af[mt][3] = __float_as_uint(p[(g + 8) * 36 + tg + 4]);
            }
#pragma unroll
            for (int nt = 0; nt < 2; nt++) {
                const float* pb = P + (wn + nt * 8 + g) * 36 + kb;
                const float* qb = Q + (wn + nt * 8 + g) * 36 + kb;
                const unsigned int p0 = __float_as_uint(pb[tg]);
                const unsigned int p1 = __float_as_uint(pb[tg + 4]);
                const unsigned int q0 = __float_as_uint(qb[tg]);
                const unsigned int q1 = __float_as_uint(qb[tg + 4]);
#pragma unroll
                for (int mt = 0; mt < 4; mt++) {
                    mma8(c1a[mt][nt], af[mt], p0, p1);
                    mma8(c3a[mt][nt], af[mt], q0, q1);
                }
            }
        }
        if (kt + 1 < KT) sts((kt + 1) & 1);
        __syncthreads();
    }

    const float* b1p = B1v + (size_t)z * Nh + nBase;
    const float* b3p = B3v + (size_t)z * Nh + nBase;
#pragma unroll
    for (int mt = 0; mt < 4; mt++) {
#pragma unroll
        for (int nt = 0; nt < 2; nt++) {
#pragma unroll
            for (int i = 0; i < 4; i++) {
                const int rl = wm + mt * 16 + g + ((i >> 1) << 3);
                const int cl = wn + nt * 8 + (tg << 1) + (i & 1);
                const float v1 = c1a[mt][nt][i] + __ldg(b1p + cl);
                const float v3 = c3a[mt][nt][i] + __ldg(b3p + cl);
                const float sig = 1.f / (1.f + expf(-v1));
                g_H[(size_t)(rowOff + rl) * Nh + nBase + cl] = v1 * sig * v3;
            }
        }
    }
}

// ---------------- 4) sparse per-expert down-projection ----------------
// Y[slot, n] = sw[slot] * (H[slot] @ W2[e]^T + b2[e])[n]
__global__ void __launch_bounds__(256, 1)
g2_sparse(const float* __restrict__ w2, const float* __restrict__ b2) {
    extern __shared__ float sm[];
    float* As = sm;                  // [2][128][36]
    float* Bs = sm + 2 * 128 * 36;   // [2][128][36]

    const int e = blockIdx.z;
    const int mBase = blockIdx.y * 128;
    if (mBase >= g_cnt[e]) return;
    const int slot0 = g_base[e] + mBase;
    const int nBase = blockIdx.x * 128;

    const int tid = threadIdx.x;
    const int row0 = tid >> 3;
    const int kc = (tid & 7) << 2;
    const int warp = tid >> 5, lane = tid & 31;
    const int g = lane >> 2, tg = lane & 3;
    const int wm = (warp & 1) << 6;
    const int wn = (warp >> 1) << 5;

    float acc[4][4][4];
#pragma unroll
    for (int a = 0; a < 4; a++)
#pragma unroll
        for (int b = 0; b < 4; b++)
#pragma unroll
            for (int c = 0; c < 4; c++) acc[a][b][c] = 0.f;

    float4 ar[4], br[4];
    const float* Abase = g_H + (size_t)slot0 * HDIM;
    const float* Bbase = w2 + ((size_t)e * DDIM + nBase) * HDIM;

    auto ldg = [&](int kt) {
        const int kk = kt * 32 + kc;
#pragma unroll
        for (int i = 0; i < 4; i++) {
            ar[i] = *(const float4*)(Abase + (size_t)(row0 + 32 * i) * HDIM + kk);
            br[i] = *(const float4*)(Bbase + (size_t)(row0 + 32 * i) * HDIM + kk);
        }
    };
    auto sts = [&](int buf) {
        float* Ab = As + buf * (128 * 36);
        float* Bb = Bs + buf * (128 * 36);
#pragma unroll
        for (int i = 0; i < 4; i++) {
            const int r = row0 + 32 * i;
            float4 a = ar[i], b = br[i];
            *(float4*)(Ab + r * 36 + kc) =
                make_float4(tf32r(a.x), tf32r(a.y), tf32r(a.z), tf32r(a.w));
            *(float4*)(Bb + r * 36 + kc) =
                make_float4(tf32r(b.x), tf32r(b.y), tf32r(b.z), tf32r(b.w));
        }
    };

    ldg(0);
    sts(0);
    __syncthreads();

    const int KT = HDIM / 32;   // 64
    for (int kt = 0; kt < KT; kt++) {
        const int cur = kt & 1;
        if (kt + 1 < KT) ldg(kt + 1);
        const float* Ab = As + cur * (128 * 36);
        const float* Bb = Bs + cur * (128 * 36);
#pragma unroll
        for (int ks = 0; ks < 4; ks++) {
            const int kb = ks * 8;
            unsigned int af[4][4];
#pragma unroll
            for (int mt = 0; mt < 4; mt++) {
                const float* p = Ab + (wm + mt * 16) * 36 + kb;
                af[mt][0] = __float_as_uint(p[g * 36 + tg]);
                af[mt][1] = __float_as_uint(p[(g + 8) * 36 + tg]);
                af[mt][2] = __float_as_uint(p[g * 36 + tg + 4]);
                af[mt][3] = __float_as_uint(p[(g + 8) * 36 + tg + 4]);
            }
#pragma unroll
            for (int nt = 0; nt < 4; nt++) {
                const float* q = Bb + (wn + nt * 8 + g) * 36 + kb;
                const unsigned int b0 = __float_as_uint(q[tg]);
                const unsigned int b1_ = __float_as_uint(q[tg + 4]);
#pragma unroll
                for (int mt = 0; mt < 4; mt++) mma8(acc[mt][nt], af[mt], b0, b1_);
            }
        }
        if (kt + 1 < KT) sts((kt + 1) & 1);
        __syncthreads();
    }

    const float* b2p = b2 + (size_t)e * DDIM + nBase;
#pragma unroll
    for (int mt = 0; mt < 4; mt++) {
#pragma unroll
        for (int i = 0; i < 4; i++) {
            const int rl = wm + mt * 16 + g + ((i >> 1) << 3);
            const int slot = slot0 + rl;
            const float swv = __ldg(g_sw + slot);
#pragma unroll
            for (int nt = 0; nt < 4; nt++) {
                const int cl = wn + nt * 8 + (tg << 1) + (i & 1);
                g_Y[(size_t)slot * DDIM + nBase + cl] =
                    swv * (acc[mt][nt][i] + __ldg(b2p + cl));
            }
        }
    }
}

// ---------------- 6) shared-expert projection + routed combine ----------------
// out[t] = Hs[t] @ SW2^T + sb2 + Y[pos0[t]] + Y[pos1[t]]
__global__ void __launch_bounds__(256, 1)
g_final(const float* __restrict__ B, const float* __restrict__ bias,
        float* __restrict__ out) {
    extern __shared__ float sm[];
    float* As = sm;                  // [2][128][36]
    float* Bs = sm + 2 * 128 * 36;   // [2][128][36]

    const int tid = threadIdx.x;
    const int mBase = blockIdx.y * 128;
    const int nBase = blockIdx.x * 128;

    const int row0 = tid >> 3;
    const int kc = (tid & 7) << 2;
    const int warp = tid >> 5, lane = tid & 31;
    const int g = lane >> 2, tg = lane & 3;
    const int wm = (warp & 1) << 6;
    const int wn = (warp >> 1) << 5;

    float acc[4][4][4];
#pragma unroll
    for (int a = 0; a < 4; a++)
#pragma unroll
        for (int b = 0; b < 4; b++)
#pragma unroll
            for (int c = 0; c < 4; c++) acc[a][b][c] = 0.f;

    float4 ar[4], br[4];
    const float* Abase = g_H + (size_t)mBase * HSDIM;
    const float* Bbase = B   + (size_t)nBase * HSDIM;

    auto ldg = [&](int kt) {
        const int kk = kt * 32 + kc;
#pragma unroll
        for (int i = 0; i < 4; i++) {
            ar[i] = *(const float4*)(Abase + (size_t)(row0 + 32 * i) * HSDIM + kk);
            br[i] = *(const float4*)(Bbase + (size_t)(row0 + 32 * i) * HSDIM + kk);
        }
    };
    auto sts = [&](int buf) {
        float* Ab = As + buf * (128 * 36);
        float* Bb = Bs + buf * (128 * 36);
#pragma unroll
        for (int i = 0; i < 4; i++) {
            const int r = row0 + 32 * i;
            float4 a = ar[i], b = br[i];
            *(float4*)(Ab + r * 36 + kc) =
                make_float4(tf32r(a.x), tf32r(a.y), tf32r(a.z), tf32r(a.w));
            *(float4*)(Bb + r * 36 + kc) =
                make_float4(tf32r(b.x), tf32r(b.y), tf32r(b.z), tf32r(b.w));
        }
    };

    ldg(0);
    sts(0);
    __syncthreads();

    const int KT = HSDIM / 32;  // 128
    for (int kt = 0; kt < KT; kt++) {
        const int cur = kt & 1;
        if (kt + 1 < KT) ldg(kt + 1);
        const float* Ab = As + cur * (128 * 36);
        const float* Bb = Bs + cur * (128 * 36);
#pragma unroll
        for (int ks = 0; ks < 4; ks++) {
            const int kb = ks * 8;
            unsigned int af[4][4];
#pragma unroll
            for (int mt = 0; mt < 4; mt++) {
                const float* p = Ab + (wm + mt * 16) * 36 + kb;
                af[mt][0] = __float_as_uint(p[g * 36 + tg]);
                af[mt][1] = __float_as_uint(p[(g + 8) * 36 + tg]);
                af[mt][2] = __float_as_uint(p[g * 36 + tg + 4]);
                af[mt][3] = __float_as_uint(p[(g + 8) * 36 + tg + 4]);
            }
#pragma unroll
            for (int nt = 0; nt < 4; nt++) {
                const float* q = Bb + (wn + nt * 8 + g) * 36 + kb;
                const unsigned int b0 = __float_as_uint(q[tg]);
                const unsigned int b1_ = __float_as_uint(q[tg + 4]);
#pragma unroll
                for (int mt = 0; mt < 4; mt++) mma8(acc[mt][nt], af[mt], b0, b1_);
            }
        }
        if (kt + 1 < KT) sts((kt + 1) & 1);
        __syncthreads();
    }

#pragma unroll
    for (int mt = 0; mt < 4; mt++) {
#pragma unroll
        for (int i = 0; i < 4; i++) {
            const int rl = wm + mt * 16 + g + ((i >> 1) << 3);
            const int t = mBase + rl;
            const int p0 = __ldg(g_pos + 2 * t);
            const int p1 = __ldg(g_pos + 2 * t + 1);
            const float* y0 = g_Y + (size_t)p0 * DDIM + nBase;
            const float* y1 = g_Y + (size_t)p1 * DDIM + nBase;
#pragma unroll
            for (int nt = 0; nt < 4; nt++) {
                const int cl = wn + nt * 8 + (tg << 1) + (i & 1);
                out[(size_t)t * DDIM + nBase + cl] =
                    acc[mt][nt][i] + __ldg(bias + nBase + cl) +
                    __ldg(y0 + cl) + __ldg(y1 + cl);
            }
        }
    }
}

// ---------------- launcher ----------------

extern "C" void kernel_launch(void* const* d_in, const int* in_sizes, int n_in,
                              void* d_out, int out_size) {
    const float* x   = (const float*)d_in[0];
    const float* gw  = (const float*)d_in[1];
    const float* gb  = (const float*)d_in[2];
    const float* w1  = (const float*)d_in[3];
    const float* b1  = (const float*)d_in[4];
    const float* w2  = (const float*)d_in[5];
    const float* b2  = (const float*)d_in[6];
    const float* w3  = (const float*)d_in[7];
    const float* b3  = (const float*)d_in[8];
    const float* sw1 = (const float*)d_in[9];
    const float* sb1 = (const float*)d_in[10];
    const float* sw2 = (const float*)d_in[11];
    const float* sb2 = (const float*)d_in[12];
    const float* sw3 = (const float*)d_in[13];
    const float* sb3 = (const float*)d_in[14];
    float* out = (float*)d_out;

    const int SMEM_G1 = (2 * 128 * 36 + 4 * 64 * 36) * 4;   // 73728 B
    const int SMEM_GG = (4 * 128 * 36) * 4;                 // 73728 B

    cudaFuncSetAttribute(g1_swiglu<true>,
                         cudaFuncAttributeMaxDynamicSharedMemorySize, SMEM_G1);
    cudaFuncSetAttribute(g1_swiglu<false>,
                         cudaFuncAttributeMaxDynamicSharedMemorySize, SMEM_G1);
    cudaFuncSetAttribute(g2_sparse,
                         cudaFuncAttributeMaxDynamicSharedMemorySize, SMEM_GG);
    cudaFuncSetAttribute(g_final,
                         cudaFuncAttributeMaxDynamicSharedMemorySize, SMEM_GG);

    // 1) gate -> top-2 ids/weights
    gate_kernel<<<NTOK / 8, 256>>>(x, gw, gb);

    // 2) deterministic dispatch tables
    scan_dispatch<<<NEXP, 256>>>();

    // 3) sparse routed SwiGLU (early-exit tiles beyond each expert's count)
    g1_swiglu<true><<<dim3(HDIM / 64, 64, NEXP), 256, SMEM_G1>>>(
        x, w1, b1, w3, b3, HDIM);

    // 4) sparse routed down-projection -> g_Y
    g2_sparse<<<dim3(DDIM / 128, 64, NEXP), 256, SMEM_GG>>>(w2, b2);

    // 5) shared-expert SwiGLU hidden (dense, reuses g_H as [N][HS])
    g1_swiglu<false><<<dim3(HSDIM / 64, NTOK / 128, 1), 256, SMEM_G1>>>(
        x, sw1, sb1, sw3, sb3, HSDIM);

    // 6) shared projection + routed combine -> out (single write)
    g_final<<<dim3(DDIM / 128, NTOK / 128), 256, SMEM_GG>>>(sw2, sb2, out);
}

// round 13
// speedup vs baseline: 3.0148x; 1.2338x over previous
#include <cuda_runtime.h>
#include <cuda_bf16.h>
#include <cstdint>

// ---------------------------------------------------------------------------
// MoE forward, GB300 (sm_103a harness targets sm_103 -> no tcgen05).
// Round 5: mma.sync tf32 + cp.async producers + pre-rounded operands,
// WITH the cp.async wait_group fix on the final iteration (R4 bug: at the last
// k-tile only one group is pending so wait_group 1 passed without completing
// it -> stale last k-slab -> rel_err 4.8e-3).
//   N=8192 tokens, D=1024, H=2048, E=8, TOP_K=2, HS=4096.
// Pipeline (deterministic, graph-capturable):
//   1) gate_kernel    -> per-token top-2 ids + renormalized weights
//   2) scan_dispatch  -> deterministic per-expert slot permutation
//   3) round_copy x7  -> tf32-RNA pre-rounded copies of X and all GEMM weights
//   4) g1_cp<true>    -> H[slot] = silu(Xr W1r^T+b1)*(Xr W3r^T+b3)  (stored tf32)
//   5) g2_cp          -> Y[slot] = sw[slot]*(H W2r^T + b2)
//   6) g1_cp<false>   -> Hs = shared-expert SwiGLU (stored tf32)
//   7) gf_cp          -> out[t] = Hs SW2r^T + sb2 + Y[pos0[t]] + Y[pos1[t]]
// ---------------------------------------------------------------------------

#define NTOK   8192
#define DDIM   1024
#define HDIM   2048
#define NEXP   8
#define HSDIM  4096
#define MAXSLOT (NTOK * 2 + NEXP * 128)   // 17408

// Scratch
__device__ float g_H[(size_t)36 * 1024 * 1024];
__device__ float g_Y[(size_t)MAXSLOT * DDIM];
__device__ float g_Wr[(size_t)72 * 1024 * 1024];   // pre-rounded operands
__device__ int   g_ti[NTOK * 2];
__device__ float g_tw[NTOK * 2];
__device__ int   g_pos[NTOK * 2];
__device__ int   g_gather[MAXSLOT];
__device__ float g_sw[MAXSLOT];
__device__ int   g_cnt[NEXP];
__device__ int   g_base[NEXP];

// pre-rounded operand offsets (floats)
#define OFF_XR   ((size_t)0)
#define OFF_W1   (OFF_XR  + (size_t)NTOK * DDIM)
#define OFF_W3   (OFF_W1  + (size_t)NEXP * HDIM * DDIM)
#define OFF_W2   (OFF_W3  + (size_t)NEXP * HDIM * DDIM)
#define OFF_SW1  (OFF_W2  + (size_t)NEXP * DDIM * HDIM)
#define OFF_SW3  (OFF_SW1 + (size_t)HSDIM * DDIM)
#define OFF_SW2  (OFF_SW3 + (size_t)HSDIM * DDIM)

// ---------------- helpers ----------------

__device__ __forceinline__ float tf32r(float x) {
    unsigned int u;
    asm("cvt.rna.tf32.f32 %0, %1;" : "=r"(u) : "f"(x));
    return __uint_as_float(u);
}

__device__ __forceinline__ void mma8(float c[4], const unsigned int a[4],
                                     unsigned int b0, unsigned int b1) {
    asm volatile(
        "mma.sync.aligned.m16n8k8.row.col.f32.tf32.tf32.f32 "
        "{%0,%1,%2,%3},{%4,%5,%6,%7},{%8,%9},{%0,%1,%2,%3};\n"
        : "+f"(c[0]), "+f"(c[1]), "+f"(c[2]), "+f"(c[3])
        : "r"(a[0]), "r"(a[1]), "r"(a[2]), "r"(a[3]), "r"(b0), "r"(b1));
}

__device__ __forceinline__ uint32_t smem_u32(const void* p) {
    uint32_t a;
    asm("{ .reg .u64 t; cvta.to.shared.u64 t, %1; cvt.u32.u64 %0, t; }"
        : "=r"(a) : "l"(p));
    return a;
}
#define CP_ASYNC16(sm, gp) \
    asm volatile("cp.async.cg.shared.global [%0], [%1], 16;" :: "r"(sm), "l"(gp))
#define CP_COMMIT() asm volatile("cp.async.commit_group;" ::: "memory")
#define CP_WAIT1()  asm volatile("cp.async.wait_group 1;" ::: "memory")
#define CP_WAIT0()  asm volatile("cp.async.wait_group 0;" ::: "memory")

// ---------------- rounding pass ----------------
__global__ void round_copy(float* __restrict__ dst, const float* __restrict__ src,
                           int n4) {
    const int i = blockIdx.x * blockDim.x + threadIdx.x;
    if (i < n4) {
        float4 v = ((const float4*)src)[i];
        ((float4*)dst)[i] =
            make_float4(tf32r(v.x), tf32r(v.y), tf32r(v.z), tf32r(v.w));
    }
}

// ---------------- 1) gate ----------------
__global__ void gate_kernel(const float* __restrict__ x,
                            const float* __restrict__ gw,
                            const float* __restrict__ gb) {
    const int warp = threadIdx.x >> 5, lane = threadIdx.x & 31;
    const int token = blockIdx.x * 8 + warp;
    const float* xr = x + (size_t)token * DDIM;
    float acc[NEXP];
#pragma unroll
    for (int e = 0; e < NEXP; e++) acc[e] = 0.f;
    for (int d = lane; d < DDIM; d += 32) {
        const float xv = xr[d];
#pragma unroll
        for (int e = 0; e < NEXP; e++) acc[e] += xv * gw[e * DDIM + d];
    }
#pragma unroll
    for (int e = 0; e < NEXP; e++) {
#pragma unroll
        for (int off = 16; off > 0; off >>= 1)
            acc[e] += __shfl_xor_sync(0xffffffffu, acc[e], off);
    }
    if (lane == 0) {
        float mx = -1e30f;
#pragma unroll
        for (int e = 0; e < NEXP; e++) { acc[e] += gb[e]; mx = fmaxf(mx, acc[e]); }
        float s[NEXP], sum = 0.f;
#pragma unroll
        for (int e = 0; e < NEXP; e++) { s[e] = expf(acc[e] - mx); sum += s[e]; }
        const float inv = 1.f / sum;
        int i1 = 0, i2 = 0;
        float v1 = -1.f, v2 = -1.f;
#pragma unroll
        for (int e = 0; e < NEXP; e++) {
            const float sc = s[e] * inv;
            if (sc > v1)      { v2 = v1; i2 = i1; v1 = sc; i1 = e; }
            else if (sc > v2) { v2 = sc; i2 = e; }
        }
        const float den = 1.f / (v1 + v2 + 1e-20f);
        g_ti[token * 2]     = i1;
        g_ti[token * 2 + 1] = i2;
        g_tw[token * 2]     = v1 * den;
        g_tw[token * 2 + 1] = v2 * den;
    }
}

// ---------------- 2) deterministic dispatch ----------------
__global__ void scan_dispatch() {
    const int e = blockIdx.x;
    const int tid = threadIdx.x;
    __shared__ int s_scan[256];
    __shared__ int s_cnt[NEXP];
    if (tid < NEXP) s_cnt[tid] = 0;
    __syncthreads();

    int ca[NEXP];
#pragma unroll
    for (int k = 0; k < NEXP; k++) ca[k] = 0;
    int my = 0;
    const int t0 = tid * 32;
    for (int i = 0; i < 32; i++) {
        const int t = t0 + i;
        const int e0 = g_ti[2 * t], e1 = g_ti[2 * t + 1];
        ca[e0]++; ca[e1]++;
        if (e0 == e || e1 == e) my++;
    }
#pragma unroll
    for (int k = 0; k < NEXP; k++) atomicAdd(&s_cnt[k], ca[k]);
    s_scan[tid] = my;
    __syncthreads();
    for (int off = 1; off < 256; off <<= 1) {
        int v = (tid >= off) ? s_scan[tid - off] : 0;
        __syncthreads();
        s_scan[tid] += v;
        __syncthreads();
    }
    int base = 0;
#pragma unroll
    for (int k = 0; k < NEXP; k++)
        if (k < e) base += ((s_cnt[k] + 127) >> 7) << 7;

    int pos = base + s_scan[tid] - my;
    for (int i = 0; i < 32; i++) {
        const int t = t0 + i;
#pragma unroll
        for (int k = 0; k < 2; k++) {
            if (g_ti[2 * t + k] == e) {
                g_pos[2 * t + k] = pos;
                g_gather[pos] = t;
                g_sw[pos] = g_tw[2 * t + k];
                pos++;
            }
        }
    }
    const int cnt = s_cnt[e];
    const int padEnd = ((cnt + 127) >> 7) << 7;
    for (int p = cnt + tid; p < padEnd; p += 256) {
        g_gather[base + p] = 0;
        g_sw[base + p] = 0.f;
    }
    if (tid == 0) { g_cnt[e] = cnt; g_base[e] = base; }
}

// ---------------- 3/5) dual-GEMM SwiGLU (cp.async producer) ----------------
template <bool SPARSE>
__global__ void __launch_bounds__(256, 2)
g1_cp(const float* __restrict__ B1v, const float* __restrict__ B3v, int Nh,
      size_t offW1, size_t offW3) {
    extern __shared__ float sm[];
    float* As  = sm;                          // [2][128][36]
    float* B1s = sm + 2 * 128 * 36;           // [2][64][36]
    float* B3s = B1s + 2 * 64 * 36;           // [2][64][36]
    const uint32_t uA  = smem_u32(As);
    const uint32_t uB1 = smem_u32(B1s);
    const uint32_t uB3 = smem_u32(B3s);

    const int z = blockIdx.z;
    const int mBase = blockIdx.y * 128;
    int rowOff = mBase;
    if (SPARSE) {
        if (mBase >= g_cnt[z]) return;
        rowOff = g_base[z] + mBase;
    }
    const int nBase = blockIdx.x * 64;
    const float* X   = g_Wr + OFF_XR;
    const float* w1z = g_Wr + offW1 + ((size_t)z * Nh + nBase) * DDIM;
    const float* w3z = g_Wr + offW3 + ((size_t)z * Nh + nBase) * DDIM;

    const int tid = threadIdx.x;
    const int row0 = tid >> 3;
    const int kc4 = (tid & 7) << 2;
    const int warp = tid >> 5, lane = tid & 31;
    const int g = lane >> 2, tg = lane & 3;
    const int wm = (warp & 1) << 6;
    const int wn = (warp >> 1) << 4;

    int tokA[4];
#pragma unroll
    for (int i = 0; i < 4; i++) {
        const int r = row0 + 32 * i;
        tokA[i] = SPARSE ? g_gather[rowOff + r] : (mBase + r);
    }

    float c1a[4][2][4], c3a[4][2][4];
#pragma unroll
    for (int a = 0; a < 4; a++)
#pragma unroll
        for (int b = 0; b < 2; b++)
#pragma unroll
            for (int c = 0; c < 4; c++) { c1a[a][b][c] = 0.f; c3a[a][b][c] = 0.f; }

    auto issue = [&](int kt) {
        const int buf = kt & 1;
        const int kk = kt * 32 + kc4;
#pragma unroll
        for (int i = 0; i < 4; i++) {
            const int r = row0 + 32 * i;
            CP_ASYNC16(uA + (buf * 128 * 36 + r * 36 + kc4) * 4,
                       X + (size_t)tokA[i] * DDIM + kk);
        }
#pragma unroll
        for (int i = 0; i < 2; i++) {
            const int r = row0 + 32 * i;
            CP_ASYNC16(uB1 + (buf * 64 * 36 + r * 36 + kc4) * 4,
                       w1z + (size_t)r * DDIM + kk);
            CP_ASYNC16(uB3 + (buf * 64 * 36 + r * 36 + kc4) * 4,
                       w3z + (size_t)r * DDIM + kk);
        }
        CP_COMMIT();
    };

    const int KT = DDIM / 32;   // 32
    issue(0);
    issue(1);
    for (int kt = 0; kt < KT; kt++) {
        const int cur = kt & 1;
        // FIX: last iteration has only its own group pending -> must wait 0.
        if (kt + 1 < KT) { CP_WAIT1(); } else { CP_WAIT0(); }
        __syncthreads();
        const float* Ab = As + cur * (128 * 36);
        const float* P  = B1s + cur * (64 * 36);
        const float* Q  = B3s + cur * (64 * 36);
#pragma unroll
        for (int ks = 0; ks < 4; ks++) {
            const int kb = ks * 8;
            unsigned int af[4][4];
#pragma unroll
            for (int mt = 0; mt < 4; mt++) {
                const float* p = Ab + (wm + mt * 16) * 36 + kb;
                af[mt][0] = __float_as_uint(p[g * 36 + tg]);
                af[mt][1] = __float_as_uint(p[(g + 8) * 36 + tg]);
                af[mt][2] = __float_as_uint(p[g * 36 + tg + 4]);
                af[mt][3] = __float_as_uint(p[(g + 8) * 36 + tg + 4]);
            }
#pragma unroll
            for (int nt = 0; nt < 2; nt++) {
                const float* pb = P + (wn + nt * 8 + g) * 36 + kb;
                const float* qb = Q + (wn + nt * 8 + g) * 36 + kb;
                const unsigned int p0 = __float_as_uint(pb[tg]);
                const unsigned int p1 = __float_as_uint(pb[tg + 4]);
                const unsigned int q0 = __float_as_uint(qb[tg]);
                const unsigned int q1 = __float_as_uint(qb[tg + 4]);
#pragma unroll
                for (int mt = 0; mt < 4; mt++) {
                    mma8(c1a[mt][nt], af[mt], p0, p1);
                    mma8(c3a[mt][nt], af[mt], q0, q1);
                }
            }
        }
        __syncthreads();
        if (kt + 2 < KT) issue(kt + 2);
    }

    const float* b1p = B1v + (size_t)z * Nh + nBase;
    const float* b3p = B3v + (size_t)z * Nh + nBase;
#pragma unroll
    for (int mt = 0; mt < 4; mt++) {
#pragma unroll
        for (int nt = 0; nt < 2; nt++) {
#pragma unroll
            for (int i = 0; i < 4; i++) {
                const int rl = wm + mt * 16 + g + ((i >> 1) << 3);
                const int cl = wn + nt * 8 + (tg << 1) + (i & 1);
                const float v1 = c1a[mt][nt][i] + __ldg(b1p + cl);
                const float v3 = c3a[mt][nt][i] + __ldg(b3p + cl);
                const float sig = 1.f / (1.f + expf(-v1));
                g_H[(size_t)(rowOff + rl) * Nh + nBase + cl] = tf32r(v1 * sig * v3);
            }
        }
    }
}

// ---------------- 4) sparse per-expert down-projection ----------------
__global__ void __launch_bounds__(256, 2)
g2_cp(const float* __restrict__ b2) {
    extern __shared__ float sm[];
    float* As = sm;                  // [2][128][36]
    float* Bs = sm + 2 * 128 * 36;   // [2][128][36]
    const uint32_t uA = smem_u32(As);
    const uint32_t uB = smem_u32(Bs);

    const int e = blockIdx.z;
    const int mBase = blockIdx.y * 128;
    if (mBase >= g_cnt[e]) return;
    const int slot0 = g_base[e] + mBase;
    const int nBase = blockIdx.x * 128;

    const int tid = threadIdx.x;
    const int row0 = tid >> 3;
    const int kc4 = (tid & 7) << 2;
    const int warp = tid >> 5, lane = tid & 31;
    const int g = lane >> 2, tg = lane & 3;
    const int wm = (warp & 1) << 6;
    const int wn = (warp >> 1) << 5;

    float acc[4][4][4];
#pragma unroll
    for (int a = 0; a < 4; a++)
#pragma unroll
        for (int b = 0; b < 4; b++)
#pragma unroll
            for (int c = 0; c < 4; c++) acc[a][b][c] = 0.f;

    const float* Abase = g_H + (size_t)slot0 * HDIM;
    const float* Bbase = g_Wr + OFF_W2 + ((size_t)e * DDIM + nBase) * HDIM;

    auto issue = [&](int kt) {
        const int buf = kt & 1;
        const int kk = kt * 32 + kc4;
#pragma unroll
        for (int i = 0; i < 4; i++) {
            const int r = row0 + 32 * i;
            CP_ASYNC16(uA + (buf * 128 * 36 + r * 36 + kc4) * 4,
                       Abase + (size_t)r * HDIM + kk);
            CP_ASYNC16(uB + (buf * 128 * 36 + r * 36 + kc4) * 4,
                       Bbase + (size_t)r * HDIM + kk);
        }
        CP_COMMIT();
    };

    const int KT = HDIM / 32;   // 64
    issue(0);
    issue(1);
    for (int kt = 0; kt < KT; kt++) {
        const int cur = kt & 1;
        if (kt + 1 < KT) { CP_WAIT1(); } else { CP_WAIT0(); }
        __syncthreads();
        const float* Ab = As + cur * (128 * 36);
        const float* Bb = Bs + cur * (128 * 36);
#pragma unroll
        for (int ks = 0; ks < 4; ks++) {
            const int kb = ks * 8;
            unsigned int af[4][4];
#pragma unroll
            for (int mt = 0; mt < 4; mt++) {
                const float* p = Ab + (wm + mt * 16) * 36 + kb;
                af[mt][0] = __float_as_uint(p[g * 36 + tg]);
                af[mt][1] = __float_as_uint(p[(g + 8) * 36 + tg]);
                af[mt][2] = __float_as_uint(p[g * 36 + tg + 4]);
                af[mt][3] = __float_as_uint(p[(g + 8) * 36 + tg + 4]);
            }
#pragma unroll
            for (int nt = 0; nt < 4; nt++) {
                const float* q = Bb + (wn + nt * 8 + g) * 36 + kb;
                const unsigned int b0 = __float_as_uint(q[tg]);
                const unsigned int b1_ = __float_as_uint(q[tg + 4]);
#pragma unroll
                for (int mt = 0; mt < 4; mt++) mma8(acc[mt][nt], af[mt], b0, b1_);
            }
        }
        __syncthreads();
        if (kt + 2 < KT) issue(kt + 2);
    }

    const float* b2p = b2 + (size_t)e * DDIM + nBase;
#pragma unroll
    for (int mt = 0; mt < 4; mt++) {
#pragma unroll
        for (int i = 0; i < 4; i++) {
            const int rl = wm + mt * 16 + g + ((i >> 1) << 3);
            const int slot = slot0 + rl;
            const float swv = __ldg(g_sw + slot);
#pragma unroll
            for (int nt = 0; nt < 4; nt++) {
                const int cl = wn + nt * 8 + (tg << 1) + (i & 1);
                g_Y[(size_t)slot * DDIM + nBase + cl] =
                    swv * (acc[mt][nt][i] + __ldg(b2p + cl));
            }
        }
    }
}

// ---------------- 7) shared projection + routed combine ----------------
__global__ void __launch_bounds__(256, 2)
gf_cp(const float* __restrict__ bias, float* __restrict__ out) {
    extern __shared__ float sm[];
    float* As = sm;
    float* Bs = sm + 2 * 128 * 36;
    const uint32_t uA = smem_u32(As);
    const uint32_t uB = smem_u32(Bs);

    const int tid = threadIdx.x;
    const int mBase = blockIdx.y * 128;
    const int nBase = blockIdx.x * 128;

    const int row0 = tid >> 3;
    const int kc4 = (tid & 7) << 2;
    const int warp = tid >> 5, lane = tid & 31;
    const int g = lane >> 2, tg = lane & 3;
    const int wm = (warp & 1) << 6;
    const int wn = (warp >> 1) << 5;

    float acc[4][4][4];
#pragma unroll
    for (int a = 0; a < 4; a++)
#pragma unroll
        for (int b = 0; b < 4; b++)
#pragma unroll
            for (int c = 0; c < 4; c++) acc[a][b][c] = 0.f;

    const float* Abase = g_H + (size_t)mBase * HSDIM;
    const float* Bbase = g_Wr + OFF_SW2 + (size_t)nBase * HSDIM;

    auto issue = [&](int kt) {
        const int buf = kt & 1;
        const int kk = kt * 32 + kc4;
#pragma unroll
        for (int i = 0; i < 4; i++) {
            const int r = row0 + 32 * i;
            CP_ASYNC16(uA + (buf * 128 * 36 + r * 36 + kc4) * 4,
                       Abase + (size_t)r * HSDIM + kk);
            CP_ASYNC16(uB + (buf * 128 * 36 + r * 36 + kc4) * 4,
                       Bbase + (size_t)r * HSDIM + kk);
        }
        CP_COMMIT();
    };

    const int KT = HSDIM / 32;  // 128
    issue(0);
    issue(1);
    for (int kt = 0; kt < KT; kt++) {
        const int cur = kt & 1;
        if (kt + 1 < KT) { CP_WAIT1(); } else { CP_WAIT0(); }
        __syncthreads();
        const float* Ab = As + cur * (128 * 36);
        const float* Bb = Bs + cur * (128 * 36);
#pragma unroll
        for (int ks = 0; ks < 4; ks++) {
            const int kb = ks * 8;
            unsigned int af[4][4];
#pragma unroll
            for (int mt = 0; mt < 4; mt++) {
                const float* p = Ab + (wm + mt * 16) * 36 + kb;
                af[mt][0] = __float_as_uint(p[g * 36 + tg]);
                af[mt][1] = __float_as_uint(p[(g + 8) * 36 + tg]);
                af[mt][2] = __float_as_uint(p[g * 36 + tg + 4]);
                af[mt][3] = __float_as_uint(p[(g + 8) * 36 + tg + 4]);
            }
#pragma unroll
            for (int nt = 0; nt < 4; nt++) {
                const float* q = Bb + (wn + nt * 8 + g) * 36 + kb;
                const unsigned int b0 = __float_as_uint(q[tg]);
                const unsigned int b1_ = __float_as_uint(q[tg + 4]);
#pragma unroll
                for (int mt = 0; mt < 4; mt++) mma8(acc[mt][nt], af[mt], b0, b1_);
            }
        }
        __syncthreads();
        if (kt + 2 < KT) issue(kt + 2);
    }

#pragma unroll
    for (int mt = 0; mt < 4; mt++) {
#pragma unroll
        for (int i = 0; i < 4; i++) {
            const int rl = wm + mt * 16 + g + ((i >> 1) << 3);
            const int t = mBase + rl;
            const int p0 = __ldg(g_pos + 2 * t);
            const int p1 = __ldg(g_pos + 2 * t + 1);
            const float* y0 = g_Y + (size_t)p0 * DDIM + nBase;
            const float* y1 = g_Y + (size_t)p1 * DDIM + nBase;
#pragma unroll
            for (int nt = 0; nt < 4; nt++) {
                const int cl = wn + nt * 8 + (tg << 1) + (i & 1);
                out[(size_t)t * DDIM + nBase + cl] =
                    acc[mt][nt][i] + __ldg(bias + nBase + cl) +
                    __ldg(y0 + cl) + __ldg(y1 + cl);
            }
        }
    }
}

// ---------------- launcher ----------------

extern "C" void kernel_launch(void* const* d_in, const int* in_sizes, int n_in,
                              void* d_out, int out_size) {
    const float* x   = (const float*)d_in[0];
    const float* gw  = (const float*)d_in[1];
    const float* gb  = (const float*)d_in[2];
    const float* w1  = (const float*)d_in[3];
    const float* b1  = (const float*)d_in[4];
    const float* w2  = (const float*)d_in[5];
    const float* b2  = (const float*)d_in[6];
    const float* w3  = (const float*)d_in[7];
    const float* b3  = (const float*)d_in[8];
    const float* sw1 = (const float*)d_in[9];
    const float* sb1 = (const float*)d_in[10];
    const float* sw2 = (const float*)d_in[11];
    const float* sb2 = (const float*)d_in[12];
    const float* sw3 = (const float*)d_in[13];
    const float* sb3 = (const float*)d_in[14];
    float* out = (float*)d_out;

    float* wr = nullptr;
    cudaGetSymbolAddress((void**)&wr, g_Wr);

    const int SMEM_G1 = (2 * 128 * 36 + 4 * 64 * 36) * 4;   // 73728 B
    const int SMEM_GG = (4 * 128 * 36) * 4;                 // 73728 B

    cudaFuncSetAttribute(g1_cp<true>,
                         cudaFuncAttributeMaxDynamicSharedMemorySize, SMEM_G1);
    cudaFuncSetAttribute(g1_cp<false>,
                         cudaFuncAttributeMaxDynamicSharedMemorySize, SMEM_G1);
    cudaFuncSetAttribute(g2_cp,
                         cudaFuncAttributeMaxDynamicSharedMemorySize, SMEM_GG);
    cudaFuncSetAttribute(gf_cp,
                         cudaFuncAttributeMaxDynamicSharedMemorySize, SMEM_GG);

    // 1) gate
    gate_kernel<<<NTOK / 8, 256>>>(x, gw, gb);
    // 2) dispatch tables
    scan_dispatch<<<NEXP, 256>>>();

    // 3) pre-round GEMM operands to tf32
    auto rc = [&](size_t off, const float* src, size_t n) {
        const int n4 = (int)(n / 4);
        round_copy<<<(n4 + 255) / 256, 256>>>(wr + off, src, n4);
    };
    rc(OFF_XR,  x,   (size_t)NTOK * DDIM);
    rc(OFF_W1,  w1,  (size_t)NEXP * HDIM * DDIM);
    rc(OFF_W3,  w3,  (size_t)NEXP * HDIM * DDIM);
    rc(OFF_W2,  w2,  (size_t)NEXP * DDIM * HDIM);
    rc(OFF_SW1, sw1, (size_t)HSDIM * DDIM);
    rc(OFF_SW3, sw3, (size_t)HSDIM * DDIM);
    rc(OFF_SW2, sw2, (size_t)DDIM * HSDIM);

    // 4) sparse routed SwiGLU -> H (tf32)
    g1_cp<true><<<dim3(HDIM / 64, 64, NEXP), 256, SMEM_G1>>>(
        b1, b3, HDIM, OFF_W1, OFF_W3);
    // 5) sparse routed down-projection -> Y
    g2_cp<<<dim3(DDIM / 128, 64, NEXP), 256, SMEM_GG>>>(b2);
    // 6) shared-expert SwiGLU (dense) -> Hs (tf32)
    g1_cp<false><<<dim3(HSDIM / 64, NTOK / 128, 1), 256, SMEM_G1>>>(
        sb1, sb3, HSDIM, OFF_SW1, OFF_SW3);
    // 7) shared projection + combine -> out
    gf_cp<<<dim3(DDIM / 128, NTOK / 128), 256, SMEM_GG>>>(sb2, out);
}

// round 15
// speedup vs baseline: 5.5302x; 1.8344x over previous
#include <cuda_runtime.h>
#include <cuda_fp16.h>
#include <cstdint>

// ---------------------------------------------------------------------------
// MoE forward, GB300 (harness targets sm_103 -> no tcgen05).
// Round 7: fp16 mma.sync (m16n8k16, fp32 accum), FIXED A-fragment row bug
// (R14 dropped the lane-group `g` from the A row index -> rel_err 1.32).
//   N=8192 tokens, D=1024, H=2048, E=8, TOP_K=2, HS=4096.
// Pipeline (deterministic, graph-capturable):
//   1) gate_kernel   -> per-token top-2 ids + renormalized weights (fp32 exact)
//   2) scan_dispatch -> deterministic per-expert slot permutation
//   3) to_half x7    -> fp16-RN copies of X and all GEMM weights
//   4) g1_cp<true>   -> H[slot] = silu(Xh W1h^T+b1)*(Xh W3h^T+b3)  (H fp16)
//   5) g2_cp         -> Y[slot] = sw[slot]*(H W2h^T + b2)          (Y fp32)
//   6) g1_cp<false>  -> Hs = shared-expert SwiGLU (fp16)
//   7) gf_cp         -> out[t] = Hs SW2h^T + sb2 + Y[pos0[t]] + Y[pos1[t]]
// GEMM core: mma.sync.m16n8k16 f16->f32, 128-wide tiles, K-slabs of 64 halves,
// 2-stage cp.async pipeline, padded smem (72-half rows = 36 u32), 2 CTAs/SM.
// ---------------------------------------------------------------------------

#define NTOK   8192
#define DDIM   1024
#define HDIM   2048
#define NEXP   8
#define HSDIM  4096
#define MAXSLOT (NTOK * 2 + NEXP * 128)   // 17408

// Scratch
__device__ __half g_Wh[(size_t)72 * 1024 * 1024];  // fp16 operand pool
__device__ __half g_H[(size_t)36 * 1024 * 1024];   // hidden scratch
__device__ float  g_Y[(size_t)MAXSLOT * DDIM];
__device__ int    g_ti[NTOK * 2];
__device__ float  g_tw[NTOK * 2];
__device__ int    g_pos[NTOK * 2];
__device__ int    g_gather[MAXSLOT];
__device__ float  g_sw[MAXSLOT];
__device__ int    g_cnt[NEXP];
__device__ int    g_base[NEXP];

// operand offsets (in halves)
#define OFF_XR   ((size_t)0)
#define OFF_W1   (OFF_XR  + (size_t)NTOK * DDIM)
#define OFF_W3   (OFF_W1  + (size_t)NEXP * HDIM * DDIM)
#define OFF_W2   (OFF_W3  + (size_t)NEXP * HDIM * DDIM)
#define OFF_SW1  (OFF_W2  + (size_t)NEXP * DDIM * HDIM)
#define OFF_SW3  (OFF_SW1 + (size_t)HSDIM * DDIM)
#define OFF_SW2  (OFF_SW3 + (size_t)HSDIM * DDIM)

// smem row stride: 72 halves = 36 u32 = 144 B (conflict-free, 16B-aligned)
#define SROW32 36
#define SROWH  72

// ---------------- helpers ----------------

__device__ __forceinline__ void mma16(float c[4], const unsigned int a[4],
                                      unsigned int b0, unsigned int b1) {
    asm volatile(
        "mma.sync.aligned.m16n8k16.row.col.f32.f16.f16.f32 "
        "{%0,%1,%2,%3},{%4,%5,%6,%7},{%8,%9},{%0,%1,%2,%3};\n"
        : "+f"(c[0]), "+f"(c[1]), "+f"(c[2]), "+f"(c[3])
        : "r"(a[0]), "r"(a[1]), "r"(a[2]), "r"(a[3]), "r"(b0), "r"(b1));
}

__device__ __forceinline__ uint32_t smem_u32(const void* p) {
    uint32_t a;
    asm("{ .reg .u64 t; cvta.to.shared.u64 t, %1; cvt.u32.u64 %0, t; }"
        : "=r"(a) : "l"(p));
    return a;
}
#define CP_ASYNC16(sm, gp) \
    asm volatile("cp.async.cg.shared.global [%0], [%1], 16;" :: "r"(sm), "l"(gp))
#define CP_COMMIT() asm volatile("cp.async.commit_group;" ::: "memory")
#define CP_WAIT1()  asm volatile("cp.async.wait_group 1;" ::: "memory")
#define CP_WAIT0()  asm volatile("cp.async.wait_group 0;" ::: "memory")

// ---------------- fp16 conversion pass ----------------
__global__ void to_half(__half* __restrict__ dst, const float* __restrict__ src,
                        int n4) {
    const int i = blockIdx.x * blockDim.x + threadIdx.x;
    if (i < n4) {
        float4 v = ((const float4*)src)[i];
        __half2 h0 = __floats2half2_rn(v.x, v.y);
        __half2 h1 = __floats2half2_rn(v.z, v.w);
        uint2 u;
        u.x = *reinterpret_cast<uint32_t*>(&h0);
        u.y = *reinterpret_cast<uint32_t*>(&h1);
        ((uint2*)dst)[i] = u;
    }
}

// ---------------- 1) gate ----------------
__global__ void gate_kernel(const float* __restrict__ x,
                            const float* __restrict__ gw,
                            const float* __restrict__ gb) {
    const int warp = threadIdx.x >> 5, lane = threadIdx.x & 31;
    const int token = blockIdx.x * 8 + warp;
    const float* xr = x + (size_t)token * DDIM;
    float acc[NEXP];
#pragma unroll
    for (int e = 0; e < NEXP; e++) acc[e] = 0.f;
    for (int d = lane; d < DDIM; d += 32) {
        const float xv = xr[d];
#pragma unroll
        for (int e = 0; e < NEXP; e++) acc[e] += xv * gw[e * DDIM + d];
    }
#pragma unroll
    for (int e = 0; e < NEXP; e++) {
#pragma unroll
        for (int off = 16; off > 0; off >>= 1)
            acc[e] += __shfl_xor_sync(0xffffffffu, acc[e], off);
    }
    if (lane == 0) {
        float mx = -1e30f;
#pragma unroll
        for (int e = 0; e < NEXP; e++) { acc[e] += gb[e]; mx = fmaxf(mx, acc[e]); }
        float s[NEXP], sum = 0.f;
#pragma unroll
        for (int e = 0; e < NEXP; e++) { s[e] = expf(acc[e] - mx); sum += s[e]; }
        const float inv = 1.f / sum;
        int i1 = 0, i2 = 0;
        float v1 = -1.f, v2 = -1.f;
#pragma unroll
        for (int e = 0; e < NEXP; e++) {
            const float sc = s[e] * inv;
            if (sc > v1)      { v2 = v1; i2 = i1; v1 = sc; i1 = e; }
            else if (sc > v2) { v2 = sc; i2 = e; }
        }
        const float den = 1.f / (v1 + v2 + 1e-20f);
        g_ti[token * 2]     = i1;
        g_ti[token * 2 + 1] = i2;
        g_tw[token * 2]     = v1 * den;
        g_tw[token * 2 + 1] = v2 * den;
    }
}

// ---------------- 2) deterministic dispatch ----------------
__global__ void scan_dispatch() {
    const int e = blockIdx.x;
    const int tid = threadIdx.x;
    __shared__ int s_scan[256];
    __shared__ int s_cnt[NEXP];
    if (tid < NEXP) s_cnt[tid] = 0;
    __syncthreads();

    int ca[NEXP];
#pragma unroll
    for (int k = 0; k < NEXP; k++) ca[k] = 0;
    int my = 0;
    const int t0 = tid * 32;
    for (int i = 0; i < 32; i++) {
        const int t = t0 + i;
        const int e0 = g_ti[2 * t], e1 = g_ti[2 * t + 1];
        ca[e0]++; ca[e1]++;
        if (e0 == e || e1 == e) my++;
    }
#pragma unroll
    for (int k = 0; k < NEXP; k++) atomicAdd(&s_cnt[k], ca[k]);
    s_scan[tid] = my;
    __syncthreads();
    for (int off = 1; off < 256; off <<= 1) {
        int v = (tid >= off) ? s_scan[tid - off] : 0;
        __syncthreads();
        s_scan[tid] += v;
        __syncthreads();
    }
    int base = 0;
#pragma unroll
    for (int k = 0; k < NEXP; k++)
        if (k < e) base += ((s_cnt[k] + 127) >> 7) << 7;

    int pos = base + s_scan[tid] - my;
    for (int i = 0; i < 32; i++) {
        const int t = t0 + i;
#pragma unroll
        for (int k = 0; k < 2; k++) {
            if (g_ti[2 * t + k] == e) {
                g_pos[2 * t + k] = pos;
                g_gather[pos] = t;
                g_sw[pos] = g_tw[2 * t + k];
                pos++;
            }
        }
    }
    const int cnt = s_cnt[e];
    const int padEnd = ((cnt + 127) >> 7) << 7;
    for (int p = cnt + tid; p < padEnd; p += 256) {
        g_gather[base + p] = 0;
        g_sw[base + p] = 0.f;
    }
    if (tid == 0) { g_cnt[e] = cnt; g_base[e] = base; }
}

// ---------------- 3/5) dual-GEMM SwiGLU (fp16 mma) ----------------
template <bool SPARSE>
__global__ void __launch_bounds__(256, 2)
g1_cp(const float* __restrict__ B1v, const float* __restrict__ B3v, int Nh,
      size_t offW1, size_t offW3) {
    extern __shared__ __half smh[];
    __half* As  = smh;                              // [2][128][72] halves
    __half* B1s = smh + 2 * 128 * SROWH;            // [2][64][72]
    __half* B3s = B1s + 2 * 64 * SROWH;             // [2][64][72]
    const uint32_t uA  = smem_u32(As);
    const uint32_t uB1 = smem_u32(B1s);
    const uint32_t uB3 = smem_u32(B3s);

    const int z = blockIdx.z;
    const int mBase = blockIdx.y * 128;
    int rowOff = mBase;
    if (SPARSE) {
        if (mBase >= g_cnt[z]) return;
        rowOff = g_base[z] + mBase;
    }
    const int nBase = blockIdx.x * 64;
    const __half* X   = g_Wh + OFF_XR;
    const __half* w1z = g_Wh + offW1 + ((size_t)z * Nh + nBase) * DDIM;
    const __half* w3z = g_Wh + offW3 + ((size_t)z * Nh + nBase) * DDIM;

    const int tid = threadIdx.x;
    const int row0 = tid >> 3;                 // 0..31
    const int cc   = tid & 7;                  // 16B chunk within 64-half row
    const int warp = tid >> 5, lane = tid & 31;
    const int g = lane >> 2, tg = lane & 3;
    const int wm = (warp & 1) << 6;
    const int wn = (warp >> 1) << 4;

    int tokA[4];
#pragma unroll
    for (int i = 0; i < 4; i++) {
        const int r = row0 + 32 * i;
        tokA[i] = SPARSE ? g_gather[rowOff + r] : (mBase + r);
    }

    float c1a[4][2][4], c3a[4][2][4];
#pragma unroll
    for (int a = 0; a < 4; a++)
#pragma unroll
        for (int b = 0; b < 2; b++)
#pragma unroll
            for (int c = 0; c < 4; c++) { c1a[a][b][c] = 0.f; c3a[a][b][c] = 0.f; }

    auto issue = [&](int kt) {
        const int buf = kt & 1;
        const int kk = kt * 64 + cc * 8;       // half offset
#pragma unroll
        for (int i = 0; i < 4; i++) {
            const int r = row0 + 32 * i;
            CP_ASYNC16(uA + (buf * 128 * SROWH + r * SROWH + cc * 8) * 2,
                       X + (size_t)tokA[i] * DDIM + kk);
        }
#pragma unroll
        for (int i = 0; i < 2; i++) {
            const int r = row0 + 32 * i;
            CP_ASYNC16(uB1 + (buf * 64 * SROWH + r * SROWH + cc * 8) * 2,
                       w1z + (size_t)r * DDIM + kk);
            CP_ASYNC16(uB3 + (buf * 64 * SROWH + r * SROWH + cc * 8) * 2,
                       w3z + (size_t)r * DDIM + kk);
        }
        CP_COMMIT();
    };

    const int KT = DDIM / 64;   // 16
    issue(0);
    issue(1);
    for (int kt = 0; kt < KT; kt++) {
        const int cur = kt & 1;
        if (kt + 1 < KT) { CP_WAIT1(); } else { CP_WAIT0(); }
        __syncthreads();
        const uint32_t* Ab = (const uint32_t*)(As  + cur * (128 * SROWH));
        const uint32_t* P  = (const uint32_t*)(B1s + cur * (64 * SROWH));
        const uint32_t* Q  = (const uint32_t*)(B3s + cur * (64 * SROWH));
#pragma unroll
        for (int ks = 0; ks < 4; ks++) {       // 4 x k16
            const int kb = ks * 8;             // u32 offset within row
            unsigned int af[4][4];
#pragma unroll
            for (int mt = 0; mt < 4; mt++) {
                // FIX: A fragment row includes lane-group g
                const uint32_t* p = Ab + (wm + mt * 16 + g) * SROW32 + kb;
                af[mt][0] = p[tg];                     // row g-part, k-low
                af[mt][1] = p[8 * SROW32 + tg];        // row +8,     k-low
                af[mt][2] = p[tg + 4];                 // row g-part, k-high
                af[mt][3] = p[8 * SROW32 + tg + 4];    // row +8,     k-high
            }
#pragma unroll
            for (int nt = 0; nt < 2; nt++) {
                const uint32_t* pb = P + (wn + nt * 8 + g) * SROW32 + kb;
                const uint32_t* qb = Q + (wn + nt * 8 + g) * SROW32 + kb;
                const unsigned int p0 = pb[tg], p1 = pb[tg + 4];
                const unsigned int q0 = qb[tg], q1 = qb[tg + 4];
#pragma unroll
                for (int mt = 0; mt < 4; mt++) {
                    mma16(c1a[mt][nt], af[mt], p0, p1);
                    mma16(c3a[mt][nt], af[mt], q0, q1);
                }
            }
        }
        __syncthreads();
        if (kt + 2 < KT) issue(kt + 2);
    }

    // epilogue: SwiGLU, store H as fp16 (half2 pairs: cols tg*2, tg*2+1)
    const float* b1p = B1v + (size_t)z * Nh + nBase;
    const float* b3p = B3v + (size_t)z * Nh + nBase;
#pragma unroll
    for (int mt = 0; mt < 4; mt++) {
#pragma unroll
        for (int nt = 0; nt < 2; nt++) {
            const int cl0 = wn + nt * 8 + (tg << 1);
            const float bb1a = __ldg(b1p + cl0),     bb3a = __ldg(b3p + cl0);
            const float bb1b = __ldg(b1p + cl0 + 1), bb3b = __ldg(b3p + cl0 + 1);
#pragma unroll
            for (int h = 0; h < 2; h++) {      // h=0: row g, h=1: row g+8
                const int rl = wm + mt * 16 + g + (h << 3);
                const float v1a = c1a[mt][nt][2 * h]     + bb1a;
                const float v1b = c1a[mt][nt][2 * h + 1] + bb1b;
                const float v3a = c3a[mt][nt][2 * h]     + bb3a;
                const float v3b = c3a[mt][nt][2 * h + 1] + bb3b;
                const float oa = v1a * (1.f / (1.f + expf(-v1a))) * v3a;
                const float ob = v1b * (1.f / (1.f + expf(-v1b))) * v3b;
                *(__half2*)(g_H + (size_t)(rowOff + rl) * Nh + nBase + cl0) =
                    __floats2half2_rn(oa, ob);
            }
        }
    }
}

// ---------------- 4) sparse per-expert down-projection ----------------
__global__ void __launch_bounds__(256, 2)
g2_cp(const float* __restrict__ b2) {
    extern __shared__ __half smh[];
    __half* As = smh;                          // [2][128][72]
    __half* Bs = smh + 2 * 128 * SROWH;        // [2][128][72]
    const uint32_t uA = smem_u32(As);
    const uint32_t uB = smem_u32(Bs);

    const int e = blockIdx.z;
    const int mBase = blockIdx.y * 128;
    if (mBase >= g_cnt[e]) return;
    const int slot0 = g_base[e] + mBase;
    const int nBase = blockIdx.x * 128;

    const int tid = threadIdx.x;
    const int row0 = tid >> 3;
    const int cc   = tid & 7;
    const int warp = tid >> 5, lane = tid & 31;
    const int g = lane >> 2, tg = lane & 3;
    const int wm = (warp & 1) << 6;
    const int wn = (warp >> 1) << 5;

    float acc[4][4][4];
#pragma unroll
    for (int a = 0; a < 4; a++)
#pragma unroll
        for (int b = 0; b < 4; b++)
#pragma unroll
            for (int c = 0; c < 4; c++) acc[a][b][c] = 0.f;

    const __half* Abase = g_H + (size_t)slot0 * HDIM;
    const __half* Bbase = g_Wh + OFF_W2 + ((size_t)e * DDIM + nBase) * HDIM;

    auto issue = [&](int kt) {
        const int buf = kt & 1;
        const int kk = kt * 64 + cc * 8;
#pragma unroll
        for (int i = 0; i < 4; i++) {
            const int r = row0 + 32 * i;
            CP_ASYNC16(uA + (buf * 128 * SROWH + r * SROWH + cc * 8) * 2,
                       Abase + (size_t)r * HDIM + kk);
            CP_ASYNC16(uB + (buf * 128 * SROWH + r * SROWH + cc * 8) * 2,
                       Bbase + (size_t)r * HDIM + kk);
        }
        CP_COMMIT();
    };

    const int KT = HDIM / 64;   // 32
    issue(0);
    issue(1);
    for (int kt = 0; kt < KT; kt++) {
        const int cur = kt & 1;
        if (kt + 1 < KT) { CP_WAIT1(); } else { CP_WAIT0(); }
        __syncthreads();
        const uint32_t* Ab = (const uint32_t*)(As + cur * (128 * SROWH));
        const uint32_t* Bb = (const uint32_t*)(Bs + cur * (128 * SROWH));
#pragma unroll
        for (int ks = 0; ks < 4; ks++) {
            const int kb = ks * 8;
            unsigned int af[4][4];
#pragma unroll
            for (int mt = 0; mt < 4; mt++) {
                // FIX: + g in A row
                const uint32_t* p = Ab + (wm + mt * 16 + g) * SROW32 + kb;
                af[mt][0] = p[tg];
                af[mt][1] = p[8 * SROW32 + tg];
                af[mt][2] = p[tg + 4];
                af[mt][3] = p[8 * SROW32 + tg + 4];
            }
#pragma unroll
            for (int nt = 0; nt < 4; nt++) {
                const uint32_t* q = Bb + (wn + nt * 8 + g) * SROW32 + kb;
                const unsigned int b0 = q[tg], b1_ = q[tg + 4];
#pragma unroll
                for (int mt = 0; mt < 4; mt++) mma16(acc[mt][nt], af[mt], b0, b1_);
            }
        }
        __syncthreads();
        if (kt + 2 < KT) issue(kt + 2);
    }

    const float* b2p = b2 + (size_t)e * DDIM + nBase;
#pragma unroll
    for (int mt = 0; mt < 4; mt++) {
#pragma unroll
        for (int i = 0; i < 4; i++) {
            const int rl = wm + mt * 16 + g + ((i >> 1) << 3);
            const int slot = slot0 + rl;
            const float swv = __ldg(g_sw + slot);
#pragma unroll
            for (int nt = 0; nt < 4; nt++) {
                const int cl = wn + nt * 8 + (tg << 1) + (i & 1);
                g_Y[(size_t)slot * DDIM + nBase + cl] =
                    swv * (acc[mt][nt][i] + __ldg(b2p + cl));
            }
        }
    }
}

// ---------------- 7) shared projection + routed combine ----------------
__global__ void __launch_bounds__(256, 2)
gf_cp(const float* __restrict__ bias, float* __restrict__ out) {
    extern __shared__ __half smh[];
    __half* As = smh;
    __half* Bs = smh + 2 * 128 * SROWH;
    const uint32_t uA = smem_u32(As);
    const uint32_t uB = smem_u32(Bs);

    const int tid = threadIdx.x;
    const int mBase = blockIdx.y * 128;
    const int nBase = blockIdx.x * 128;

    const int row0 = tid >> 3;
    const int cc   = tid & 7;
    const int warp = tid >> 5, lane = tid & 31;
    const int g = lane >> 2, tg = lane & 3;
    const int wm = (warp & 1) << 6;
    const int wn = (warp >> 1) << 5;

    float acc[4][4][4];
#pragma unroll
    for (int a = 0; a < 4; a++)
#pragma unroll
        for (int b = 0; b < 4; b++)
#pragma unroll
            for (int c = 0; c < 4; c++) acc[a][b][c] = 0.f;

    const __half* Abase = g_H + (size_t)mBase * HSDIM;
    const __half* Bbase = g_Wh + OFF_SW2 + (size_t)nBase * HSDIM;

    auto issue = [&](int kt) {
        const int buf = kt & 1;
        const int kk = kt * 64 + cc * 8;
#pragma unroll
        for (int i = 0; i < 4; i++) {
            const int r = row0 + 32 * i;
            CP_ASYNC16(uA + (buf * 128 * SROWH + r * SROWH + cc * 8) * 2,
                       Abase + (size_t)r * HSDIM + kk);
            CP_ASYNC16(uB + (buf * 128 * SROWH + r * SROWH + cc * 8) * 2,
                       Bbase + (size_t)r * HSDIM + kk);
        }
        CP_COMMIT();
    };

    const int KT = HSDIM / 64;  // 64
    issue(0);
    issue(1);
    for (int kt = 0; kt < KT; kt++) {
        const int cur = kt & 1;
        if (kt + 1 < KT) { CP_WAIT1(); } else { CP_WAIT0(); }
        __syncthreads();
        const uint32_t* Ab = (const uint32_t*)(As + cur * (128 * SROWH));
        const uint32_t* Bb = (const uint32_t*)(Bs + cur * (128 * SROWH));
#pragma unroll
        for (int ks = 0; ks < 4; ks++) {
            const int kb = ks * 8;
            unsigned int af[4][4];
#pragma unroll
            for (int mt = 0; mt < 4; mt++) {
                // FIX: + g in A row
                const uint32_t* p = Ab + (wm + mt * 16 + g) * SROW32 + kb;
                af[mt][0] = p[tg];
                af[mt][1] = p[8 * SROW32 + tg];
                af[mt][2] = p[tg + 4];
                af[mt][3] = p[8 * SROW32 + tg + 4];
            }
#pragma unroll
            for (int nt = 0; nt < 4; nt++) {
                const uint32_t* q = Bb + (wn + nt * 8 + g) * SROW32 + kb;
                const unsigned int b0 = q[tg], b1_ = q[tg + 4];
#pragma unroll
                for (int mt = 0; mt < 4; mt++) mma16(acc[mt][nt], af[mt], b0, b1_);
            }
        }
        __syncthreads();
        if (kt + 2 < KT) issue(kt + 2);
    }

#pragma unroll
    for (int mt = 0; mt < 4; mt++) {
#pragma unroll
        for (int i = 0; i < 4; i++) {
            const int rl = wm + mt * 16 + g + ((i >> 1) << 3);
            const int t = mBase + rl;
            const int p0 = __ldg(g_pos + 2 * t);
            const int p1 = __ldg(g_pos + 2 * t + 1);
            const float* y0 = g_Y + (size_t)p0 * DDIM + nBase;
            const float* y1 = g_Y + (size_t)p1 * DDIM + nBase;
#pragma unroll
            for (int nt = 0; nt < 4; nt++) {
                const int cl = wn + nt * 8 + (tg << 1) + (i & 1);
                out[(size_t)t * DDIM + nBase + cl] =
                    acc[mt][nt][i] + __ldg(bias + nBase + cl) +
                    __ldg(y0 + cl) + __ldg(y1 + cl);
            }
        }
    }
}

// ---------------- launcher ----------------

extern "C" void kernel_launch(void* const* d_in, const int* in_sizes, int n_in,
                              void* d_out, int out_size) {
    const float* x   = (const float*)d_in[0];
    const float* gw  = (const float*)d_in[1];
    const float* gb  = (const float*)d_in[2];
    const float* w1  = (const float*)d_in[3];
    const float* b1  = (const float*)d_in[4];
    const float* w2  = (const float*)d_in[5];
    const float* b2  = (const float*)d_in[6];
    const float* w3  = (const float*)d_in[7];
    const float* b3  = (const float*)d_in[8];
    const float* sw1 = (const float*)d_in[9];
    const float* sb1 = (const float*)d_in[10];
    const float* sw2 = (const float*)d_in[11];
    const float* sb2 = (const float*)d_in[12];
    const float* sw3 = (const float*)d_in[13];
    const float* sb3 = (const float*)d_in[14];
    float* out = (float*)d_out;

    __half* wh = nullptr;
    cudaGetSymbolAddress((void**)&wh, g_Wh);

    const int SMEM_G1 = (2 * 128 * SROWH + 4 * 64 * SROWH) * 2;  // 73728 B
    const int SMEM_GG = (4 * 128 * SROWH) * 2;                   // 73728 B

    cudaFuncSetAttribute(g1_cp<true>,
                         cudaFuncAttributeMaxDynamicSharedMemorySize, SMEM_G1);
    cudaFuncSetAttribute(g1_cp<false>,
                         cudaFuncAttributeMaxDynamicSharedMemorySize, SMEM_G1);
    cudaFuncSetAttribute(g2_cp,
                         cudaFuncAttributeMaxDynamicSharedMemorySize, SMEM_GG);
    cudaFuncSetAttribute(gf_cp,
                         cudaFuncAttributeMaxDynamicSharedMemorySize, SMEM_GG);

    // 1) gate (fp32 exact)
    gate_kernel<<<NTOK / 8, 256>>>(x, gw, gb);
    // 2) dispatch tables
    scan_dispatch<<<NEXP, 256>>>();

    // 3) convert GEMM operands to fp16
    auto cv = [&](size_t off, const float* src, size_t n) {
        const int n4 = (int)(n / 4);
        to_half<<<(n4 + 255) / 256, 256>>>(wh + off, src, n4);
    };
    cv(OFF_XR,  x,   (size_t)NTOK * DDIM);
    cv(OFF_W1,  w1,  (size_t)NEXP * HDIM * DDIM);
    cv(OFF_W3,  w3,  (size_t)NEXP * HDIM * DDIM);
    cv(OFF_W2,  w2,  (size_t)NEXP * DDIM * HDIM);
    cv(OFF_SW1, sw1, (size_t)HSDIM * DDIM);
    cv(OFF_SW3, sw3, (size_t)HSDIM * DDIM);
    cv(OFF_SW2, sw2, (size_t)DDIM * HSDIM);

    // 4) sparse routed SwiGLU -> H (fp16)
    g1_cp<true><<<dim3(HDIM / 64, 64, NEXP), 256, SMEM_G1>>>(
        b1, b3, HDIM, OFF_W1, OFF_W3);
    // 5) sparse routed down-projection -> Y (fp32)
    g2_cp<<<dim3(DDIM / 128, 64, NEXP), 256, SMEM_GG>>>(b2);
    // 6) shared-expert SwiGLU (dense) -> Hs (fp16)
    g1_cp<false><<<dim3(HSDIM / 64, NTOK / 128, 1), 256, SMEM_G1>>>(
        sb1, sb3, HSDIM, OFF_SW1, OFF_SW3);
    // 7) shared projection + combine -> out
    gf_cp<<<dim3(DDIM / 128, NTOK / 128), 256, SMEM_GG>>>(sb2, out);
}

// round 16
// speedup vs baseline: 6.3932x; 1.1560x over previous
#include <cuda_runtime.h>
#include <cuda_fp16.h>
#include <cstdint>

// ---------------------------------------------------------------------------
// MoE forward, GB300 (harness targets sm_103 -> no tcgen05).
// Round 8: fp16 mma.sync + ldmatrix fragment loads + 3-stage cp.async
// pipeline with a single __syncthreads per k-iter.
//   N=8192 tokens, D=1024, H=2048, E=8, TOP_K=2, HS=4096.
// Pipeline (deterministic, graph-capturable):
//   to_half(X,W1,W3), gate, scan, g1<true>, to_half(W2), g2,
//   to_half(SW1,SW3), g1<false>, to_half(SW2), gf
// GEMM core: mma.sync.m16n8k16 f16->f32, 128-wide tiles, K-slabs of 64
// halves, 3-stage cp.async (wait_group 1 / 0-at-tail), ldmatrix.x4 operand
// loads, padded smem rows (72 halves = 144 B, conflict-free), 2 CTAs/SM.
// ---------------------------------------------------------------------------

#define NTOK   8192
#define DDIM   1024
#define HDIM   2048
#define NEXP   8
#define HSDIM  4096
#define MAXSLOT (NTOK * 2 + NEXP * 128)   // 17408

// Scratch
__device__ __half g_Wh[(size_t)72 * 1024 * 1024];  // fp16 operand pool
__device__ __half g_H[(size_t)36 * 1024 * 1024];   // hidden scratch
__device__ float  g_Y[(size_t)MAXSLOT * DDIM];
__device__ int    g_ti[NTOK * 2];
__device__ float  g_tw[NTOK * 2];
__device__ int    g_pos[NTOK * 2];
__device__ int    g_gather[MAXSLOT];
__device__ float  g_sw[MAXSLOT];
__device__ int    g_cnt[NEXP];
__device__ int    g_base[NEXP];

// operand offsets (in halves)
#define OFF_XR   ((size_t)0)
#define OFF_W1   (OFF_XR  + (size_t)NTOK * DDIM)
#define OFF_W3   (OFF_W1  + (size_t)NEXP * HDIM * DDIM)
#define OFF_W2   (OFF_W3  + (size_t)NEXP * HDIM * DDIM)
#define OFF_SW1  (OFF_W2  + (size_t)NEXP * DDIM * HDIM)
#define OFF_SW3  (OFF_SW1 + (size_t)HSDIM * DDIM)
#define OFF_SW2  (OFF_SW3 + (size_t)HSDIM * DDIM)

// smem row stride: 72 halves = 144 B (conflict-free for ldmatrix: row r ->
// bank phase (4r mod 32), 8 consecutive rows cover all 32 banks exactly once)
#define SROWH  72
#define SROWB  144
#define STAGES 3

// ---------------- helpers ----------------

__device__ __forceinline__ void mma16(float c[4], const unsigned int a[4],
                                      unsigned int b0, unsigned int b1) {
    asm volatile(
        "mma.sync.aligned.m16n8k16.row.col.f32.f16.f16.f32 "
        "{%0,%1,%2,%3},{%4,%5,%6,%7},{%8,%9},{%0,%1,%2,%3};\n"
        : "+f"(c[0]), "+f"(c[1]), "+f"(c[2]), "+f"(c[3])
        : "r"(a[0]), "r"(a[1]), "r"(a[2]), "r"(a[3]), "r"(b0), "r"(b1));
}

#define LDSM4(r0, r1, r2, r3, addr) \
    asm volatile("ldmatrix.sync.aligned.m8n8.x4.shared.b16 {%0,%1,%2,%3}, [%4];" \
        : "=r"(r0), "=r"(r1), "=r"(r2), "=r"(r3) : "r"(addr))

__device__ __forceinline__ uint32_t smem_u32(const void* p) {
    uint32_t a;
    asm("{ .reg .u64 t; cvta.to.shared.u64 t, %1; cvt.u32.u64 %0, t; }"
        : "=r"(a) : "l"(p));
    return a;
}
#define CP_ASYNC16(sm, gp) \
    asm volatile("cp.async.cg.shared.global [%0], [%1], 16;" :: "r"(sm), "l"(gp))
#define CP_COMMIT() asm volatile("cp.async.commit_group;" ::: "memory")
#define CP_WAIT1()  asm volatile("cp.async.wait_group 1;" ::: "memory")
#define CP_WAIT0()  asm volatile("cp.async.wait_group 0;" ::: "memory")

// ---------------- fp16 conversion pass ----------------
__global__ void to_half(__half* __restrict__ dst, const float* __restrict__ src,
                        int n4) {
    const int i = blockIdx.x * blockDim.x + threadIdx.x;
    if (i < n4) {
        float4 v = ((const float4*)src)[i];
        __half2 h0 = __floats2half2_rn(v.x, v.y);
        __half2 h1 = __floats2half2_rn(v.z, v.w);
        uint2 u;
        u.x = *reinterpret_cast<uint32_t*>(&h0);
        u.y = *reinterpret_cast<uint32_t*>(&h1);
        ((uint2*)dst)[i] = u;
    }
}

// ---------------- gate ----------------
__global__ void gate_kernel(const float* __restrict__ x,
                            const float* __restrict__ gw,
                            const float* __restrict__ gb) {
    const int warp = threadIdx.x >> 5, lane = threadIdx.x & 31;
    const int token = blockIdx.x * 8 + warp;
    const float* xr = x + (size_t)token * DDIM;
    float acc[NEXP];
#pragma unroll
    for (int e = 0; e < NEXP; e++) acc[e] = 0.f;
    for (int d = lane; d < DDIM; d += 32) {
        const float xv = xr[d];
#pragma unroll
        for (int e = 0; e < NEXP; e++) acc[e] += xv * gw[e * DDIM + d];
    }
#pragma unroll
    for (int e = 0; e < NEXP; e++) {
#pragma unroll
        for (int off = 16; off > 0; off >>= 1)
            acc[e] += __shfl_xor_sync(0xffffffffu, acc[e], off);
    }
    if (lane == 0) {
        float mx = -1e30f;
#pragma unroll
        for (int e = 0; e < NEXP; e++) { acc[e] += gb[e]; mx = fmaxf(mx, acc[e]); }
        float s[NEXP], sum = 0.f;
#pragma unroll
        for (int e = 0; e < NEXP; e++) { s[e] = expf(acc[e] - mx); sum += s[e]; }
        const float inv = 1.f / sum;
        int i1 = 0, i2 = 0;
        float v1 = -1.f, v2 = -1.f;
#pragma unroll
        for (int e = 0; e < NEXP; e++) {
            const float sc = s[e] * inv;
            if (sc > v1)      { v2 = v1; i2 = i1; v1 = sc; i1 = e; }
            else if (sc > v2) { v2 = sc; i2 = e; }
        }
        const float den = 1.f / (v1 + v2 + 1e-20f);
        g_ti[token * 2]     = i1;
        g_ti[token * 2 + 1] = i2;
        g_tw[token * 2]     = v1 * den;
        g_tw[token * 2 + 1] = v2 * den;
    }
}

// ---------------- deterministic dispatch ----------------
__global__ void scan_dispatch() {
    const int e = blockIdx.x;
    const int tid = threadIdx.x;
    __shared__ int s_scan[256];
    __shared__ int s_cnt[NEXP];
    if (tid < NEXP) s_cnt[tid] = 0;
    __syncthreads();

    int ca[NEXP];
#pragma unroll
    for (int k = 0; k < NEXP; k++) ca[k] = 0;
    int my = 0;
    const int t0 = tid * 32;
    for (int i = 0; i < 32; i++) {
        const int t = t0 + i;
        const int e0 = g_ti[2 * t], e1 = g_ti[2 * t + 1];
        ca[e0]++; ca[e1]++;
        if (e0 == e || e1 == e) my++;
    }
#pragma unroll
    for (int k = 0; k < NEXP; k++) atomicAdd(&s_cnt[k], ca[k]);
    s_scan[tid] = my;
    __syncthreads();
    for (int off = 1; off < 256; off <<= 1) {
        int v = (tid >= off) ? s_scan[tid - off] : 0;
        __syncthreads();
        s_scan[tid] += v;
        __syncthreads();
    }
    int base = 0;
#pragma unroll
    for (int k = 0; k < NEXP; k++)
        if (k < e) base += ((s_cnt[k] + 127) >> 7) << 7;

    int pos = base + s_scan[tid] - my;
    for (int i = 0; i < 32; i++) {
        const int t = t0 + i;
#pragma unroll
        for (int k = 0; k < 2; k++) {
            if (g_ti[2 * t + k] == e) {
                g_pos[2 * t + k] = pos;
                g_gather[pos] = t;
                g_sw[pos] = g_tw[2 * t + k];
                pos++;
            }
        }
    }
    const int cnt = s_cnt[e];
    const int padEnd = ((cnt + 127) >> 7) << 7;
    for (int p = cnt + tid; p < padEnd; p += 256) {
        g_gather[base + p] = 0;
        g_sw[base + p] = 0.f;
    }
    if (tid == 0) { g_cnt[e] = cnt; g_base[e] = base; }
}

// ---------------- dual-GEMM SwiGLU (fp16 mma, ldmatrix, 3-stage) ----------
template <bool SPARSE>
__global__ void __launch_bounds__(256, 2)
g1_cp(const float* __restrict__ B1v, const float* __restrict__ B3v, int Nh,
      size_t offW1, size_t offW3) {
    extern __shared__ __half smh[];
    __half* As  = smh;                                   // [3][128][72]
    __half* B1s = smh + STAGES * 128 * SROWH;            // [3][64][72]
    __half* B3s = B1s + STAGES * 64 * SROWH;             // [3][64][72]
    const uint32_t uA  = smem_u32(As);
    const uint32_t uB1 = smem_u32(B1s);
    const uint32_t uB3 = smem_u32(B3s);

    const int z = blockIdx.z;
    const int mBase = blockIdx.y * 128;
    int rowOff = mBase;
    if (SPARSE) {
        if (mBase >= g_cnt[z]) return;
        rowOff = g_base[z] + mBase;
    }
    const int nBase = blockIdx.x * 64;
    const __half* X   = g_Wh + OFF_XR;
    const __half* w1z = g_Wh + offW1 + ((size_t)z * Nh + nBase) * DDIM;
    const __half* w3z = g_Wh + offW3 + ((size_t)z * Nh + nBase) * DDIM;

    const int tid = threadIdx.x;
    const int row0 = tid >> 3;                 // 0..31
    const int cc   = tid & 7;                  // 16B chunk in 64-half row
    const int warp = tid >> 5, lane = tid & 31;
    const int g = lane >> 2, tg = lane & 3;
    const int wm = (warp & 1) << 6;
    const int wn = (warp >> 1) << 4;

    // ldmatrix per-lane address components
    const int aRow  = (lane & 7) + ((lane >> 3) & 1) * 8;   // A: bit3 -> +8 rows
    const int aKoff = (lane >> 4) * 8;                      //    bit4 -> +8 halves
    const int bRow  = (lane & 7) + ((lane >> 4) & 1) * 8;   // B: bit4 -> +8 rows (nt)
    const int bKoff = ((lane >> 3) & 1) * 8;                //    bit3 -> +8 halves

    int tokA[4];
#pragma unroll
    for (int i = 0; i < 4; i++) {
        const int r = row0 + 32 * i;
        tokA[i] = SPARSE ? g_gather[rowOff + r] : (mBase + r);
    }

    float c1a[4][2][4], c3a[4][2][4];
#pragma unroll
    for (int a = 0; a < 4; a++)
#pragma unroll
        for (int b = 0; b < 2; b++)
#pragma unroll
            for (int c = 0; c < 4; c++) { c1a[a][b][c] = 0.f; c3a[a][b][c] = 0.f; }

    auto issue = [&](int kt) {
        const int buf = kt % STAGES;
        const int kk = kt * 64 + cc * 8;
#pragma unroll
        for (int i = 0; i < 4; i++) {
            const int r = row0 + 32 * i;
            CP_ASYNC16(uA + (buf * 128 * SROWH + r * SROWH + cc * 8) * 2,
                       X + (size_t)tokA[i] * DDIM + kk);
        }
#pragma unroll
        for (int i = 0; i < 2; i++) {
            const int r = row0 + 32 * i;
            CP_ASYNC16(uB1 + (buf * 64 * SROWH + r * SROWH + cc * 8) * 2,
                       w1z + (size_t)r * DDIM + kk);
            CP_ASYNC16(uB3 + (buf * 64 * SROWH + r * SROWH + cc * 8) * 2,
                       w3z + (size_t)r * DDIM + kk);
        }
        CP_COMMIT();
    };

    const int KT = DDIM / 64;   // 16
    issue(0);
    issue(1);
    for (int kt = 0; kt < KT; kt++) {
        if (kt + 1 < KT) { CP_WAIT1(); } else { CP_WAIT0(); }
        __syncthreads();    // protects buf (kt-1)%3 for the issue below
        const int buf = kt % STAGES;
        const uint32_t aB  = uA  + buf * (128 * SROWB) +
                             (wm + aRow) * SROWB + aKoff * 2;
        const uint32_t b1B = uB1 + buf * (64 * SROWB) +
                             (wn + bRow) * SROWB + bKoff * 2;
        const uint32_t b3B = uB3 + buf * (64 * SROWB) +
                             (wn + bRow) * SROWB + bKoff * 2;
#pragma unroll
        for (int ks = 0; ks < 4; ks++) {
            const int kbyte = ks * 32;
            unsigned int af[4][4];
#pragma unroll
            for (int mt = 0; mt < 4; mt++)
                LDSM4(af[mt][0], af[mt][1], af[mt][2], af[mt][3],
                      aB + mt * (16 * SROWB) + kbyte);
            unsigned int p0, p1, p2, p3, q0, q1, q2, q3;
            LDSM4(p0, p1, p2, p3, b1B + kbyte);   // nt0 b0,b1 | nt1 b0,b1
            LDSM4(q0, q1, q2, q3, b3B + kbyte);
#pragma unroll
            for (int mt = 0; mt < 4; mt++) {
                mma16(c1a[mt][0], af[mt], p0, p1);
                mma16(c1a[mt][1], af[mt], p2, p3);
                mma16(c3a[mt][0], af[mt], q0, q1);
                mma16(c3a[mt][1], af[mt], q2, q3);
            }
        }
        if (kt + 2 < KT) issue(kt + 2);
    }

    // epilogue: SwiGLU, store H as fp16
    const float* b1p = B1v + (size_t)z * Nh + nBase;
    const float* b3p = B3v + (size_t)z * Nh + nBase;
#pragma unroll
    for (int mt = 0; mt < 4; mt++) {
#pragma unroll
        for (int nt = 0; nt < 2; nt++) {
            const int cl0 = wn + nt * 8 + (tg << 1);
            const float bb1a = __ldg(b1p + cl0),     bb3a = __ldg(b3p + cl0);
            const float bb1b = __ldg(b1p + cl0 + 1), bb3b = __ldg(b3p + cl0 + 1);
#pragma unroll
            for (int h = 0; h < 2; h++) {
                const int rl = wm + mt * 16 + g + (h << 3);
                const float v1a = c1a[mt][nt][2 * h]     + bb1a;
                const float v1b = c1a[mt][nt][2 * h + 1] + bb1b;
                const float v3a = c3a[mt][nt][2 * h]     + bb3a;
                const float v3b = c3a[mt][nt][2 * h + 1] + bb3b;
                const float oa = v1a * (1.f / (1.f + expf(-v1a))) * v3a;
                const float ob = v1b * (1.f / (1.f + expf(-v1b))) * v3b;
                *(__half2*)(g_H + (size_t)(rowOff + rl) * Nh + nBase + cl0) =
                    __floats2half2_rn(oa, ob);
            }
        }
    }
}

// ---------------- sparse per-expert down-projection ----------------
__global__ void __launch_bounds__(256, 2)
g2_cp(const float* __restrict__ b2) {
    extern __shared__ __half smh[];
    __half* As = smh;                             // [3][128][72]
    __half* Bs = smh + STAGES * 128 * SROWH;      // [3][128][72]
    const uint32_t uA = smem_u32(As);
    const uint32_t uB = smem_u32(Bs);

    const int e = blockIdx.z;
    const int mBase = blockIdx.y * 128;
    if (mBase >= g_cnt[e]) return;
    const int slot0 = g_base[e] + mBase;
    const int nBase = blockIdx.x * 128;

    const int tid = threadIdx.x;
    const int row0 = tid >> 3;
    const int cc   = tid & 7;
    const int warp = tid >> 5, lane = tid & 31;
    const int g = lane >> 2, tg = lane & 3;
    const int wm = (warp & 1) << 6;
    const int wn = (warp >> 1) << 5;

    const int aRow  = (lane & 7) + ((lane >> 3) & 1) * 8;
    const int aKoff = (lane >> 4) * 8;
    const int bRow  = (lane & 7) + ((lane >> 4) & 1) * 8;
    const int bKoff = ((lane >> 3) & 1) * 8;

    float acc[4][4][4];
#pragma unroll
    for (int a = 0; a < 4; a++)
#pragma unroll
        for (int b = 0; b < 4; b++)
#pragma unroll
            for (int c = 0; c < 4; c++) acc[a][b][c] = 0.f;

    const __half* Abase = g_H + (size_t)slot0 * HDIM;
    const __half* Bbase = g_Wh + OFF_W2 + ((size_t)e * DDIM + nBase) * HDIM;

    auto issue = [&](int kt) {
        const int buf = kt % STAGES;
        const int kk = kt * 64 + cc * 8;
#pragma unroll
        for (int i = 0; i < 4; i++) {
            const int r = row0 + 32 * i;
            CP_ASYNC16(uA + (buf * 128 * SROWH + r * SROWH + cc * 8) * 2,
                       Abase + (size_t)r * HDIM + kk);
            CP_ASYNC16(uB + (buf * 128 * SROWH + r * SROWH + cc * 8) * 2,
                       Bbase + (size_t)r * HDIM + kk);
        }
        CP_COMMIT();
    };

    const int KT = HDIM / 64;   // 32
    issue(0);
    issue(1);
    for (int kt = 0; kt < KT; kt++) {
        if (kt + 1 < KT) { CP_WAIT1(); } else { CP_WAIT0(); }
        __syncthreads();
        const int buf = kt % STAGES;
        const uint32_t aB = uA + buf * (128 * SROWB) +
                            (wm + aRow) * SROWB + aKoff * 2;
        const uint32_t bB = uB + buf * (128 * SROWB) +
                            (wn + bRow) * SROWB + bKoff * 2;
#pragma unroll
        for (int ks = 0; ks < 4; ks++) {
            const int kbyte = ks * 32;
            unsigned int af[4][4];
#pragma unroll
            for (int mt = 0; mt < 4; mt++)
                LDSM4(af[mt][0], af[mt][1], af[mt][2], af[mt][3],
                      aB + mt * (16 * SROWB) + kbyte);
            unsigned int b01[4], b23[4];
            LDSM4(b01[0], b01[1], b01[2], b01[3], bB + kbyte);              // nt0,nt1
            LDSM4(b23[0], b23[1], b23[2], b23[3], bB + 16 * SROWB + kbyte); // nt2,nt3
#pragma unroll
            for (int mt = 0; mt < 4; mt++) {
                mma16(acc[mt][0], af[mt], b01[0], b01[1]);
                mma16(acc[mt][1], af[mt], b01[2], b01[3]);
                mma16(acc[mt][2], af[mt], b23[0], b23[1]);
                mma16(acc[mt][3], af[mt], b23[2], b23[3]);
            }
        }
        if (kt + 2 < KT) issue(kt + 2);
    }

    const float* b2p = b2 + (size_t)e * DDIM + nBase;
#pragma unroll
    for (int mt = 0; mt < 4; mt++) {
#pragma unroll
        for (int i = 0; i < 4; i++) {
            const int rl = wm + mt * 16 + g + ((i >> 1) << 3);
            const int slot = slot0 + rl;
            const float swv = __ldg(g_sw + slot);
#pragma unroll
            for (int nt = 0; nt < 4; nt++) {
                const int cl = wn + nt * 8 + (tg << 1) + (i & 1);
                g_Y[(size_t)slot * DDIM + nBase + cl] =
                    swv * (acc[mt][nt][i] + __ldg(b2p + cl));
            }
        }
    }
}

// ---------------- shared projection + routed combine ----------------
__global__ void __launch_bounds__(256, 2)
gf_cp(const float* __restrict__ bias, float* __restrict__ out) {
    extern __shared__ __half smh[];
    __half* As = smh;
    __half* Bs = smh + STAGES * 128 * SROWH;
    const uint32_t uA = smem_u32(As);
    const uint32_t uB = smem_u32(Bs);

    const int tid = threadIdx.x;
    const int mBase = blockIdx.y * 128;
    const int nBase = blockIdx.x * 128;

    const int row0 = tid >> 3;
    const int cc   = tid & 7;
    const int warp = tid >> 5, lane = tid & 31;
    const int g = lane >> 2, tg = lane & 3;
    const int wm = (warp & 1) << 6;
    const int wn = (warp >> 1) << 5;

    const int aRow  = (lane & 7) + ((lane >> 3) & 1) * 8;
    const int aKoff = (lane >> 4) * 8;
    const int bRow  = (lane & 7) + ((lane >> 4) & 1) * 8;
    const int bKoff = ((lane >> 3) & 1) * 8;

    float acc[4][4][4];
#pragma unroll
    for (int a = 0; a < 4; a++)
#pragma unroll
        for (int b = 0; b < 4; b++)
#pragma unroll
            for (int c = 0; c < 4; c++) acc[a][b][c] = 0.f;

    const __half* Abase = g_H + (size_t)mBase * HSDIM;
    const __half* Bbase = g_Wh + OFF_SW2 + (size_t)nBase * HSDIM;

    auto issue = [&](int kt) {
        const int buf = kt % STAGES;
        const int kk = kt * 64 + cc * 8;
#pragma unroll
        for (int i = 0; i < 4; i++) {
            const int r = row0 + 32 * i;
            CP_ASYNC16(uA + (buf * 128 * SROWH + r * SROWH + cc * 8) * 2,
                       Abase + (size_t)r * HSDIM + kk);
            CP_ASYNC16(uB + (buf * 128 * SROWH + r * SROWH + cc * 8) * 2,
                       Bbase + (size_t)r * HSDIM + kk);
        }
        CP_COMMIT();
    };

    const int KT = HSDIM / 64;  // 64
    issue(0);
    issue(1);
    for (int kt = 0; kt < KT; kt++) {
        if (kt + 1 < KT) { CP_WAIT1(); } else { CP_WAIT0(); }
        __syncthreads();
        const int buf = kt % STAGES;
        const uint32_t aB = uA + buf * (128 * SROWB) +
                            (wm + aRow) * SROWB + aKoff * 2;
        const uint32_t bB = uB + buf * (128 * SROWB) +
                            (wn + bRow) * SROWB + bKoff * 2;
#pragma unroll
        for (int ks = 0; ks < 4; ks++) {
            const int kbyte = ks * 32;
            unsigned int af[4][4];
#pragma unroll
            for (int mt = 0; mt < 4; mt++)
                LDSM4(af[mt][0], af[mt][1], af[mt][2], af[mt][3],
                      aB + mt * (16 * SROWB) + kbyte);
            unsigned int b01[4], b23[4];
            LDSM4(b01[0], b01[1], b01[2], b01[3], bB + kbyte);
            LDSM4(b23[0], b23[1], b23[2], b23[3], bB + 16 * SROWB + kbyte);
#pragma unroll
            for (int mt = 0; mt < 4; mt++) {
                mma16(acc[mt][0], af[mt], b01[0], b01[1]);
                mma16(acc[mt][1], af[mt], b01[2], b01[3]);
                mma16(acc[mt][2], af[mt], b23[0], b23[1]);
                mma16(acc[mt][3], af[mt], b23[2], b23[3]);
            }
        }
        if (kt + 2 < KT) issue(kt + 2);
    }

#pragma unroll
    for (int mt = 0; mt < 4; mt++) {
#pragma unroll
        for (int i = 0; i < 4; i++) {
            const int rl = wm + mt * 16 + g + ((i >> 1) << 3);
            const int t = mBase + rl;
            const int p0 = __ldg(g_pos + 2 * t);
            const int p1 = __ldg(g_pos + 2 * t + 1);
            const float* y0 = g_Y + (size_t)p0 * DDIM + nBase;
            const float* y1 = g_Y + (size_t)p1 * DDIM + nBase;
#pragma unroll
            for (int nt = 0; nt < 4; nt++) {
                const int cl = wn + nt * 8 + (tg << 1) + (i & 1);
                out[(size_t)t * DDIM + nBase + cl] =
                    acc[mt][nt][i] + __ldg(bias + nBase + cl) +
                    __ldg(y0 + cl) + __ldg(y1 + cl);
            }
        }
    }
}

// ---------------- launcher ----------------

extern "C" void kernel_launch(void* const* d_in, const int* in_sizes, int n_in,
                              void* d_out, int out_size) {
    const float* x   = (const float*)d_in[0];
    const float* gw  = (const float*)d_in[1];
    const float* gb  = (const float*)d_in[2];
    const float* w1  = (const float*)d_in[3];
    const float* b1  = (const float*)d_in[4];
    const float* w2  = (const float*)d_in[5];
    const float* b2  = (const float*)d_in[6];
    const float* w3  = (const float*)d_in[7];
    const float* b3  = (const float*)d_in[8];
    const float* sw1 = (const float*)d_in[9];
    const float* sb1 = (const float*)d_in[10];
    const float* sw2 = (const float*)d_in[11];
    const float* sb2 = (const float*)d_in[12];
    const float* sw3 = (const float*)d_in[13];
    const float* sb3 = (const float*)d_in[14];
    float* out = (float*)d_out;

    __half* wh = nullptr;
    cudaGetSymbolAddress((void**)&wh, g_Wh);

    // 3-stage buffers: g1 = 3*(128+64+64)*72*2 = 110592 B; g2/gf same.
    const int SMEM_G1 = STAGES * (128 + 64 + 64) * SROWH * 2;
    const int SMEM_GG = STAGES * (128 + 128) * SROWH * 2;

    cudaFuncSetAttribute(g1_cp<true>,
                         cudaFuncAttributeMaxDynamicSharedMemorySize, SMEM_G1);
    cudaFuncSetAttribute(g1_cp<false>,
                         cudaFuncAttributeMaxDynamicSharedMemorySize, SMEM_G1);
    cudaFuncSetAttribute(g2_cp,
                         cudaFuncAttributeMaxDynamicSharedMemorySize, SMEM_GG);
    cudaFuncSetAttribute(gf_cp,
                         cudaFuncAttributeMaxDynamicSharedMemorySize, SMEM_GG);

    auto cv = [&](size_t off, const float* src, size_t n) {
        const int n4 = (int)(n / 4);
        to_half<<<(n4 + 255) / 256, 256>>>(wh + off, src, n4);
    };

    // Launch order puts g1_cp<true> at launch index 5 (ncu -s 5 -c 1 slot),
    // while respecting all dependencies.
    cv(OFF_XR,  x,   (size_t)NTOK * DDIM);                 // 0
    cv(OFF_W1,  w1,  (size_t)NEXP * HDIM * DDIM);          // 1
    cv(OFF_W3,  w3,  (size_t)NEXP * HDIM * DDIM);          // 2
    gate_kernel<<<NTOK / 8, 256>>>(x, gw, gb);             // 3
    scan_dispatch<<<NEXP, 256>>>();                        // 4
    g1_cp<true><<<dim3(HDIM / 64, 64, NEXP), 256, SMEM_G1>>>(
        b1, b3, HDIM, OFF_W1, OFF_W3);                     // 5  <- profiled
    cv(OFF_W2,  w2,  (size_t)NEXP * DDIM * HDIM);          // 6
    g2_cp<<<dim3(DDIM / 128, 64, NEXP), 256, SMEM_GG>>>(b2);   // 7
    cv(OFF_SW1, sw1, (size_t)HSDIM * DDIM);                // 8
    cv(OFF_SW3, sw3, (size_t)HSDIM * DDIM);                // 9
    g1_cp<false><<<dim3(HSDIM / 64, NTOK / 128, 1), 256, SMEM_G1>>>(
        sb1, sb3, HSDIM, OFF_SW1, OFF_SW3);                // 10
    cv(OFF_SW2, sw2, (size_t)DDIM * HSDIM);                // 11
    gf_cp<<<dim3(DDIM / 128, NTOK / 128), 256, SMEM_GG>>>(sb2, out);  // 12
}

// round 17
// speedup vs baseline: 6.6581x; 1.0414x over previous
#include <cuda_runtime.h>
#include <cuda_fp16.h>
#include <cstdint>

// ---------------------------------------------------------------------------
// MoE forward, GB300 (harness targets sm_103 -> no tcgen05).
// Round 9: R16 fp16 mma.sync GEMM cores (unchanged) + two-stream overlap:
//   main: cvX, cvW1, cvW3, g1<true>, g2, gf
//   side: gate, scan, cvW2, cvSW1, cvSW3, g1<false> (own Hs buffer), cvSW2
// Joined with events (graph-capture-safe fork/join). Conversions + gate/scan
// and the shared-expert SwiGLU overlap the routed chain.
//   N=8192 tokens, D=1024, H=2048, E=8, TOP_K=2, HS=4096.
// GEMM core: mma.sync.m16n8k16 f16->f32, 128-wide tiles, K-slabs of 64
// halves, 3-stage cp.async (wait_group 1 / 0-at-tail), ldmatrix.x4 loads,
// padded smem rows (72 halves = 144 B, conflict-free), 2 CTAs/SM.
// ---------------------------------------------------------------------------

#define NTOK   8192
#define DDIM   1024
#define HDIM   2048
#define NEXP   8
#define HSDIM  4096
#define MAXSLOT (NTOK * 2 + NEXP * 128)   // 17408

// Scratch
__device__ __half g_Wh[(size_t)72 * 1024 * 1024];  // fp16 operand pool
__device__ __half g_H[(size_t)36 * 1024 * 1024];   // routed hidden (slots)
__device__ __half g_Hs[(size_t)34 * 1024 * 1024];  // shared-expert hidden
__device__ float  g_Y[(size_t)MAXSLOT * DDIM];
__device__ int    g_ti[NTOK * 2];
__device__ float  g_tw[NTOK * 2];
__device__ int    g_pos[NTOK * 2];
__device__ int    g_gather[MAXSLOT];
__device__ float  g_sw[MAXSLOT];
__device__ int    g_cnt[NEXP];
__device__ int    g_base[NEXP];

// operand offsets (in halves)
#define OFF_XR   ((size_t)0)
#define OFF_W1   (OFF_XR  + (size_t)NTOK * DDIM)
#define OFF_W3   (OFF_W1  + (size_t)NEXP * HDIM * DDIM)
#define OFF_W2   (OFF_W3  + (size_t)NEXP * HDIM * DDIM)
#define OFF_SW1  (OFF_W2  + (size_t)NEXP * DDIM * HDIM)
#define OFF_SW3  (OFF_SW1 + (size_t)HSDIM * DDIM)
#define OFF_SW2  (OFF_SW3 + (size_t)HSDIM * DDIM)

#define SROWH  72
#define SROWB  144
#define STAGES 3

// ---------------- helpers ----------------

__device__ __forceinline__ void mma16(float c[4], const unsigned int a[4],
                                      unsigned int b0, unsigned int b1) {
    asm volatile(
        "mma.sync.aligned.m16n8k16.row.col.f32.f16.f16.f32 "
        "{%0,%1,%2,%3},{%4,%5,%6,%7},{%8,%9},{%0,%1,%2,%3};\n"
        : "+f"(c[0]), "+f"(c[1]), "+f"(c[2]), "+f"(c[3])
        : "r"(a[0]), "r"(a[1]), "r"(a[2]), "r"(a[3]), "r"(b0), "r"(b1));
}

#define LDSM4(r0, r1, r2, r3, addr) \
    asm volatile("ldmatrix.sync.aligned.m8n8.x4.shared.b16 {%0,%1,%2,%3}, [%4];" \
        : "=r"(r0), "=r"(r1), "=r"(r2), "=r"(r3) : "r"(addr))

__device__ __forceinline__ uint32_t smem_u32(const void* p) {
    uint32_t a;
    asm("{ .reg .u64 t; cvta.to.shared.u64 t, %1; cvt.u32.u64 %0, t; }"
        : "=r"(a) : "l"(p));
    return a;
}
#define CP_ASYNC16(sm, gp) \
    asm volatile("cp.async.cg.shared.global [%0], [%1], 16;" :: "r"(sm), "l"(gp))
#define CP_COMMIT() asm volatile("cp.async.commit_group;" ::: "memory")
#define CP_WAIT1()  asm volatile("cp.async.wait_group 1;" ::: "memory")
#define CP_WAIT0()  asm volatile("cp.async.wait_group 0;" ::: "memory")

// ---------------- fp16 conversion pass ----------------
__global__ void to_half(__half* __restrict__ dst, const float* __restrict__ src,
                        int n4) {
    const int i = blockIdx.x * blockDim.x + threadIdx.x;
    if (i < n4) {
        float4 v = ((const float4*)src)[i];
        __half2 h0 = __floats2half2_rn(v.x, v.y);
        __half2 h1 = __floats2half2_rn(v.z, v.w);
        uint2 u;
        u.x = *reinterpret_cast<uint32_t*>(&h0);
        u.y = *reinterpret_cast<uint32_t*>(&h1);
        ((uint2*)dst)[i] = u;
    }
}

// ---------------- gate ----------------
__global__ void gate_kernel(const float* __restrict__ x,
                            const float* __restrict__ gw,
                            const float* __restrict__ gb) {
    const int warp = threadIdx.x >> 5, lane = threadIdx.x & 31;
    const int token = blockIdx.x * 8 + warp;
    const float* xr = x + (size_t)token * DDIM;
    float acc[NEXP];
#pragma unroll
    for (int e = 0; e < NEXP; e++) acc[e] = 0.f;
    for (int d = lane; d < DDIM; d += 32) {
        const float xv = xr[d];
#pragma unroll
        for (int e = 0; e < NEXP; e++) acc[e] += xv * gw[e * DDIM + d];
    }
#pragma unroll
    for (int e = 0; e < NEXP; e++) {
#pragma unroll
        for (int off = 16; off > 0; off >>= 1)
            acc[e] += __shfl_xor_sync(0xffffffffu, acc[e], off);
    }
    if (lane == 0) {
        float mx = -1e30f;
#pragma unroll
        for (int e = 0; e < NEXP; e++) { acc[e] += gb[e]; mx = fmaxf(mx, acc[e]); }
        float s[NEXP], sum = 0.f;
#pragma unroll
        for (int e = 0; e < NEXP; e++) { s[e] = expf(acc[e] - mx); sum += s[e]; }
        const float inv = 1.f / sum;
        int i1 = 0, i2 = 0;
        float v1 = -1.f, v2 = -1.f;
#pragma unroll
        for (int e = 0; e < NEXP; e++) {
            const float sc = s[e] * inv;
            if (sc > v1)      { v2 = v1; i2 = i1; v1 = sc; i1 = e; }
            else if (sc > v2) { v2 = sc; i2 = e; }
        }
        const float den = 1.f / (v1 + v2 + 1e-20f);
        g_ti[token * 2]     = i1;
        g_ti[token * 2 + 1] = i2;
        g_tw[token * 2]     = v1 * den;
        g_tw[token * 2 + 1] = v2 * den;
    }
}

// ---------------- deterministic dispatch ----------------
__global__ void scan_dispatch() {
    const int e = blockIdx.x;
    const int tid = threadIdx.x;
    __shared__ int s_scan[256];
    __shared__ int s_cnt[NEXP];
    if (tid < NEXP) s_cnt[tid] = 0;
    __syncthreads();

    int ca[NEXP];
#pragma unroll
    for (int k = 0; k < NEXP; k++) ca[k] = 0;
    int my = 0;
    const int t0 = tid * 32;
    for (int i = 0; i < 32; i++) {
        const int t = t0 + i;
        const int e0 = g_ti[2 * t], e1 = g_ti[2 * t + 1];
        ca[e0]++; ca[e1]++;
        if (e0 == e || e1 == e) my++;
    }
#pragma unroll
    for (int k = 0; k < NEXP; k++) atomicAdd(&s_cnt[k], ca[k]);
    s_scan[tid] = my;
    __syncthreads();
    for (int off = 1; off < 256; off <<= 1) {
        int v = (tid >= off) ? s_scan[tid - off] : 0;
        __syncthreads();
        s_scan[tid] += v;
        __syncthreads();
    }
    int base = 0;
#pragma unroll
    for (int k = 0; k < NEXP; k++)
        if (k < e) base += ((s_cnt[k] + 127) >> 7) << 7;

    int pos = base + s_scan[tid] - my;
    for (int i = 0; i < 32; i++) {
        const int t = t0 + i;
#pragma unroll
        for (int k = 0; k < 2; k++) {
            if (g_ti[2 * t + k] == e) {
                g_pos[2 * t + k] = pos;
                g_gather[pos] = t;
                g_sw[pos] = g_tw[2 * t + k];
                pos++;
            }
        }
    }
    const int cnt = s_cnt[e];
    const int padEnd = ((cnt + 127) >> 7) << 7;
    for (int p = cnt + tid; p < padEnd; p += 256) {
        g_gather[base + p] = 0;
        g_sw[base + p] = 0.f;
    }
    if (tid == 0) { g_cnt[e] = cnt; g_base[e] = base; }
}

// ---------------- dual-GEMM SwiGLU (fp16 mma, ldmatrix, 3-stage) ----------
template <bool SPARSE>
__global__ void __launch_bounds__(256, 2)
g1_cp(const float* __restrict__ B1v, const float* __restrict__ B3v, int Nh,
      size_t offW1, size_t offW3, __half* __restrict__ Hout) {
    extern __shared__ __half smh[];
    __half* As  = smh;                                   // [3][128][72]
    __half* B1s = smh + STAGES * 128 * SROWH;            // [3][64][72]
    __half* B3s = B1s + STAGES * 64 * SROWH;             // [3][64][72]
    const uint32_t uA  = smem_u32(As);
    const uint32_t uB1 = smem_u32(B1s);
    const uint32_t uB3 = smem_u32(B3s);

    const int z = blockIdx.z;
    const int mBase = blockIdx.y * 128;
    int rowOff = mBase;
    if (SPARSE) {
        if (mBase >= g_cnt[z]) return;
        rowOff = g_base[z] + mBase;
    }
    const int nBase = blockIdx.x * 64;
    const __half* X   = g_Wh + OFF_XR;
    const __half* w1z = g_Wh + offW1 + ((size_t)z * Nh + nBase) * DDIM;
    const __half* w3z = g_Wh + offW3 + ((size_t)z * Nh + nBase) * DDIM;

    const int tid = threadIdx.x;
    const int row0 = tid >> 3;
    const int cc   = tid & 7;
    const int warp = tid >> 5, lane = tid & 31;
    const int g = lane >> 2, tg = lane & 3;
    const int wm = (warp & 1) << 6;
    const int wn = (warp >> 1) << 4;

    const int aRow  = (lane & 7) + ((lane >> 3) & 1) * 8;
    const int aKoff = (lane >> 4) * 8;
    const int bRow  = (lane & 7) + ((lane >> 4) & 1) * 8;
    const int bKoff = ((lane >> 3) & 1) * 8;

    int tokA[4];
#pragma unroll
    for (int i = 0; i < 4; i++) {
        const int r = row0 + 32 * i;
        tokA[i] = SPARSE ? g_gather[rowOff + r] : (mBase + r);
    }

    float c1a[4][2][4], c3a[4][2][4];
#pragma unroll
    for (int a = 0; a < 4; a++)
#pragma unroll
        for (int b = 0; b < 2; b++)
#pragma unroll
            for (int c = 0; c < 4; c++) { c1a[a][b][c] = 0.f; c3a[a][b][c] = 0.f; }

    auto issue = [&](int kt) {
        const int buf = kt % STAGES;
        const int kk = kt * 64 + cc * 8;
#pragma unroll
        for (int i = 0; i < 4; i++) {
            const int r = row0 + 32 * i;
            CP_ASYNC16(uA + (buf * 128 * SROWH + r * SROWH + cc * 8) * 2,
                       X + (size_t)tokA[i] * DDIM + kk);
        }
#pragma unroll
        for (int i = 0; i < 2; i++) {
            const int r = row0 + 32 * i;
            CP_ASYNC16(uB1 + (buf * 64 * SROWH + r * SROWH + cc * 8) * 2,
                       w1z + (size_t)r * DDIM + kk);
            CP_ASYNC16(uB3 + (buf * 64 * SROWH + r * SROWH + cc * 8) * 2,
                       w3z + (size_t)r * DDIM + kk);
        }
        CP_COMMIT();
    };

    const int KT = DDIM / 64;   // 16
    issue(0);
    issue(1);
    for (int kt = 0; kt < KT; kt++) {
        if (kt + 1 < KT) { CP_WAIT1(); } else { CP_WAIT0(); }
        __syncthreads();
        const int buf = kt % STAGES;
        const uint32_t aB  = uA  + buf * (128 * SROWB) +
                             (wm + aRow) * SROWB + aKoff * 2;
        const uint32_t b1B = uB1 + buf * (64 * SROWB) +
                             (wn + bRow) * SROWB + bKoff * 2;
        const uint32_t b3B = uB3 + buf * (64 * SROWB) +
                             (wn + bRow) * SROWB + bKoff * 2;
#pragma unroll
        for (int ks = 0; ks < 4; ks++) {
            const int kbyte = ks * 32;
            unsigned int af[4][4];
#pragma unroll
            for (int mt = 0; mt < 4; mt++)
                LDSM4(af[mt][0], af[mt][1], af[mt][2], af[mt][3],
                      aB + mt * (16 * SROWB) + kbyte);
            unsigned int p0, p1, p2, p3, q0, q1, q2, q3;
            LDSM4(p0, p1, p2, p3, b1B + kbyte);
            LDSM4(q0, q1, q2, q3, b3B + kbyte);
#pragma unroll
            for (int mt = 0; mt < 4; mt++) {
                mma16(c1a[mt][0], af[mt], p0, p1);
                mma16(c1a[mt][1], af[mt], p2, p3);
                mma16(c3a[mt][0], af[mt], q0, q1);
                mma16(c3a[mt][1], af[mt], q2, q3);
            }
        }
        if (kt + 2 < KT) issue(kt + 2);
    }

    const float* b1p = B1v + (size_t)z * Nh + nBase;
    const float* b3p = B3v + (size_t)z * Nh + nBase;
#pragma unroll
    for (int mt = 0; mt < 4; mt++) {
#pragma unroll
        for (int nt = 0; nt < 2; nt++) {
            const int cl0 = wn + nt * 8 + (tg << 1);
            const float bb1a = __ldg(b1p + cl0),     bb3a = __ldg(b3p + cl0);
            const float bb1b = __ldg(b1p + cl0 + 1), bb3b = __ldg(b3p + cl0 + 1);
#pragma unroll
            for (int h = 0; h < 2; h++) {
                const int rl = wm + mt * 16 + g + (h << 3);
                const float v1a = c1a[mt][nt][2 * h]     + bb1a;
                const float v1b = c1a[mt][nt][2 * h + 1] + bb1b;
                const float v3a = c3a[mt][nt][2 * h]     + bb3a;
                const float v3b = c3a[mt][nt][2 * h + 1] + bb3b;
                const float oa = v1a * (1.f / (1.f + expf(-v1a))) * v3a;
                const float ob = v1b * (1.f / (1.f + expf(-v1b))) * v3b;
                *(__half2*)(Hout + (size_t)(rowOff + rl) * Nh + nBase + cl0) =
                    __floats2half2_rn(oa, ob);
            }
        }
    }
}

// ---------------- sparse per-expert down-projection ----------------
__global__ void __launch_bounds__(256, 2)
g2_cp(const float* __restrict__ b2) {
    extern __shared__ __half smh[];
    __half* As = smh;                             // [3][128][72]
    __half* Bs = smh + STAGES * 128 * SROWH;      // [3][128][72]
    const uint32_t uA = smem_u32(As);
    const uint32_t uB = smem_u32(Bs);

    const int e = blockIdx.z;
    const int mBase = blockIdx.y * 128;
    if (mBase >= g_cnt[e]) return;
    const int slot0 = g_base[e] + mBase;
    const int nBase = blockIdx.x * 128;

    const int tid = threadIdx.x;
    const int row0 = tid >> 3;
    const int cc   = tid & 7;
    const int warp = tid >> 5, lane = tid & 31;
    const int g = lane >> 2, tg = lane & 3;
    const int wm = (warp & 1) << 6;
    const int wn = (warp >> 1) << 5;

    const int aRow  = (lane & 7) + ((lane >> 3) & 1) * 8;
    const int aKoff = (lane >> 4) * 8;
    const int bRow  = (lane & 7) + ((lane >> 4) & 1) * 8;
    const int bKoff = ((lane >> 3) & 1) * 8;

    float acc[4][4][4];
#pragma unroll
    for (int a = 0; a < 4; a++)
#pragma unroll
        for (int b = 0; b < 4; b++)
#pragma unroll
            for (int c = 0; c < 4; c++) acc[a][b][c] = 0.f;

    const __half* Abase = g_H + (size_t)slot0 * HDIM;
    const __half* Bbase = g_Wh + OFF_W2 + ((size_t)e * DDIM + nBase) * HDIM;

    auto issue = [&](int kt) {
        const int buf = kt % STAGES;
        const int kk = kt * 64 + cc * 8;
#pragma unroll
        for (int i = 0; i < 4; i++) {
            const int r = row0 + 32 * i;
            CP_ASYNC16(uA + (buf * 128 * SROWH + r * SROWH + cc * 8) * 2,
                       Abase + (size_t)r * HDIM + kk);
            CP_ASYNC16(uB + (buf * 128 * SROWH + r * SROWH + cc * 8) * 2,
                       Bbase + (size_t)r * HDIM + kk);
        }
        CP_COMMIT();
    };

    const int KT = HDIM / 64;   // 32
    issue(0);
    issue(1);
    for (int kt = 0; kt < KT; kt++) {
        if (kt + 1 < KT) { CP_WAIT1(); } else { CP_WAIT0(); }
        __syncthreads();
        const int buf = kt % STAGES;
        const uint32_t aB = uA + buf * (128 * SROWB) +
                            (wm + aRow) * SROWB + aKoff * 2;
        const uint32_t bB = uB + buf * (128 * SROWB) +
                            (wn + bRow) * SROWB + bKoff * 2;
#pragma unroll
        for (int ks = 0; ks < 4; ks++) {
            const int kbyte = ks * 32;
            unsigned int af[4][4];
#pragma unroll
            for (int mt = 0; mt < 4; mt++)
                LDSM4(af[mt][0], af[mt][1], af[mt][2], af[mt][3],
                      aB + mt * (16 * SROWB) + kbyte);
            unsigned int b01[4], b23[4];
            LDSM4(b01[0], b01[1], b01[2], b01[3], bB + kbyte);
            LDSM4(b23[0], b23[1], b23[2], b23[3], bB + 16 * SROWB + kbyte);
#pragma unroll
            for (int mt = 0; mt < 4; mt++) {
                mma16(acc[mt][0], af[mt], b01[0], b01[1]);
                mma16(acc[mt][1], af[mt], b01[2], b01[3]);
                mma16(acc[mt][2], af[mt], b23[0], b23[1]);
                mma16(acc[mt][3], af[mt], b23[2], b23[3]);
            }
        }
        if (kt + 2 < KT) issue(kt + 2);
    }

    const float* b2p = b2 + (size_t)e * DDIM + nBase;
#pragma unroll
    for (int mt = 0; mt < 4; mt++) {
#pragma unroll
        for (int i = 0; i < 4; i++) {
            const int rl = wm + mt * 16 + g + ((i >> 1) << 3);
            const int slot = slot0 + rl;
            const float swv = __ldg(g_sw + slot);
#pragma unroll
            for (int nt = 0; nt < 4; nt++) {
                const int cl = wn + nt * 8 + (tg << 1) + (i & 1);
                g_Y[(size_t)slot * DDIM + nBase + cl] =
                    swv * (acc[mt][nt][i] + __ldg(b2p + cl));
            }
        }
    }
}

// ---------------- shared projection + routed combine ----------------
__global__ void __launch_bounds__(256, 2)
gf_cp(const __half* __restrict__ Hs, const float* __restrict__ bias,
      float* __restrict__ out) {
    extern __shared__ __half smh[];
    __half* As = smh;
    __half* Bs = smh + STAGES * 128 * SROWH;
    const uint32_t uA = smem_u32(As);
    const uint32_t uB = smem_u32(Bs);

    const int tid = threadIdx.x;
    const int mBase = blockIdx.y * 128;
    const int nBase = blockIdx.x * 128;

    const int row0 = tid >> 3;
    const int cc   = tid & 7;
    const int warp = tid >> 5, lane = tid & 31;
    const int g = lane >> 2, tg = lane & 3;
    const int wm = (warp & 1) << 6;
    const int wn = (warp >> 1) << 5;

    const int aRow  = (lane & 7) + ((lane >> 3) & 1) * 8;
    const int aKoff = (lane >> 4) * 8;
    const int bRow  = (lane & 7) + ((lane >> 4) & 1) * 8;
    const int bKoff = ((lane >> 3) & 1) * 8;

    float acc[4][4][4];
#pragma unroll
    for (int a = 0; a < 4; a++)
#pragma unroll
        for (int b = 0; b < 4; b++)
#pragma unroll
            for (int c = 0; c < 4; c++) acc[a][b][c] = 0.f;

    const __half* Abase = Hs + (size_t)mBase * HSDIM;
    const __half* Bbase = g_Wh + OFF_SW2 + (size_t)nBase * HSDIM;

    auto issue = [&](int kt) {
        const int buf = kt % STAGES;
        const int kk = kt * 64 + cc * 8;
#pragma unroll
        for (int i = 0; i < 4; i++) {
            const int r = row0 + 32 * i;
            CP_ASYNC16(uA + (buf * 128 * SROWH + r * SROWH + cc * 8) * 2,
                       Abase + (size_t)r * HSDIM + kk);
            CP_ASYNC16(uB + (buf * 128 * SROWH + r * SROWH + cc * 8) * 2,
                       Bbase + (size_t)r * HSDIM + kk);
        }
        CP_COMMIT();
    };

    const int KT = HSDIM / 64;  // 64
    issue(0);
    issue(1);
    for (int kt = 0; kt < KT; kt++) {
        if (kt + 1 < KT) { CP_WAIT1(); } else { CP_WAIT0(); }
        __syncthreads();
        const int buf = kt % STAGES;
        const uint32_t aB = uA + buf * (128 * SROWB) +
                            (wm + aRow) * SROWB + aKoff * 2;
        const uint32_t bB = uB + buf * (128 * SROWB) +
                            (wn + bRow) * SROWB + bKoff * 2;
#pragma unroll
        for (int ks = 0; ks < 4; ks++) {
            const int kbyte = ks * 32;
            unsigned int af[4][4];
#pragma unroll
            for (int mt = 0; mt < 4; mt++)
                LDSM4(af[mt][0], af[mt][1], af[mt][2], af[mt][3],
                      aB + mt * (16 * SROWB) + kbyte);
            unsigned int b01[4], b23[4];
            LDSM4(b01[0], b01[1], b01[2], b01[3], bB + kbyte);
            LDSM4(b23[0], b23[1], b23[2], b23[3], bB + 16 * SROWB + kbyte);
#pragma unroll
            for (int mt = 0; mt < 4; mt++) {
                mma16(acc[mt][0], af[mt], b01[0], b01[1]);
                mma16(acc[mt][1], af[mt], b01[2], b01[3]);
                mma16(acc[mt][2], af[mt], b23[0], b23[1]);
                mma16(acc[mt][3], af[mt], b23[2], b23[3]);
            }
        }
        if (kt + 2 < KT) issue(kt + 2);
    }

#pragma unroll
    for (int mt = 0; mt < 4; mt++) {
#pragma unroll
        for (int i = 0; i < 4; i++) {
            const int rl = wm + mt * 16 + g + ((i >> 1) << 3);
            const int t = mBase + rl;
            const int p0 = __ldg(g_pos + 2 * t);
            const int p1 = __ldg(g_pos + 2 * t + 1);
            const float* y0 = g_Y + (size_t)p0 * DDIM + nBase;
            const float* y1 = g_Y + (size_t)p1 * DDIM + nBase;
#pragma unroll
            for (int nt = 0; nt < 4; nt++) {
                const int cl = wn + nt * 8 + (tg << 1) + (i & 1);
                out[(size_t)t * DDIM + nBase + cl] =
                    acc[mt][nt][i] + __ldg(bias + nBase + cl) +
                    __ldg(y0 + cl) + __ldg(y1 + cl);
            }
        }
    }
}

// ---------------- launcher ----------------

extern "C" void kernel_launch(void* const* d_in, const int* in_sizes, int n_in,
                              void* d_out, int out_size) {
    const float* x   = (const float*)d_in[0];
    const float* gw  = (const float*)d_in[1];
    const float* gb  = (const float*)d_in[2];
    const float* w1  = (const float*)d_in[3];
    const float* b1  = (const float*)d_in[4];
    const float* w2  = (const float*)d_in[5];
    const float* b2  = (const float*)d_in[6];
    const float* w3  = (const float*)d_in[7];
    const float* b3  = (const float*)d_in[8];
    const float* sw1 = (const float*)d_in[9];
    const float* sb1 = (const float*)d_in[10];
    const float* sw2 = (const float*)d_in[11];
    const float* sb2 = (const float*)d_in[12];
    const float* sw3 = (const float*)d_in[13];
    const float* sb3 = (const float*)d_in[14];
    float* out = (float*)d_out;

    __half* wh = nullptr;
    __half* hH = nullptr;
    __half* hHs = nullptr;
    cudaGetSymbolAddress((void**)&wh,  g_Wh);
    cudaGetSymbolAddress((void**)&hH,  g_H);
    cudaGetSymbolAddress((void**)&hHs, g_Hs);

    const int SMEM_G1 = STAGES * (128 + 64 + 64) * SROWH * 2;   // 110592
    const int SMEM_GG = STAGES * (128 + 128) * SROWH * 2;       // 110592

    cudaFuncSetAttribute(g1_cp<true>,
                         cudaFuncAttributeMaxDynamicSharedMemorySize, SMEM_G1);
    cudaFuncSetAttribute(g1_cp<false>,
                         cudaFuncAttributeMaxDynamicSharedMemorySize, SMEM_G1);
    cudaFuncSetAttribute(g2_cp,
                         cudaFuncAttributeMaxDynamicSharedMemorySize, SMEM_GG);
    cudaFuncSetAttribute(gf_cp,
                         cudaFuncAttributeMaxDynamicSharedMemorySize, SMEM_GG);

    // One-time host-side resources for two-stream overlap (no device memory).
    static bool s_init = false;
    static bool s_use = false;
    static cudaStream_t sS = nullptr;
    static cudaEvent_t evFork = nullptr, evScan = nullptr, evX = nullptr,
                       evW2 = nullptr, evJoin = nullptr;
    if (!s_init) {
        s_init = true;
        s_use =
            (cudaStreamCreateWithFlags(&sS, cudaStreamNonBlocking) == cudaSuccess) &&
            (cudaEventCreateWithFlags(&evFork, cudaEventDisableTiming) == cudaSuccess) &&
            (cudaEventCreateWithFlags(&evScan, cudaEventDisableTiming) == cudaSuccess) &&
            (cudaEventCreateWithFlags(&evX,    cudaEventDisableTiming) == cudaSuccess) &&
            (cudaEventCreateWithFlags(&evW2,   cudaEventDisableTiming) == cudaSuccess) &&
            (cudaEventCreateWithFlags(&evJoin, cudaEventDisableTiming) == cudaSuccess);
    }

    auto cvOn = [&](cudaStream_t st, size_t off, const float* src, size_t n) {
        const int n4 = (int)(n / 4);
        to_half<<<(n4 + 255) / 256, 256, 0, st>>>(wh + off, src, n4);
    };

    if (s_use) {
        // ---- main stream 0: routed chain;  side stream sS: gate/scan + shared
        cudaEventRecord(evFork, 0);
        cudaStreamWaitEvent(sS, evFork, 0);

        // side: gate + scan (independent of conversions)
        gate_kernel<<<NTOK / 8, 256, 0, sS>>>(x, gw, gb);
        scan_dispatch<<<NEXP, 256, 0, sS>>>();
        cudaEventRecord(evScan, sS);

        // main: conversions needed by routed g1
        cvOn(0, OFF_XR, x, (size_t)NTOK * DDIM);
        cudaEventRecord(evX, 0);
        cvOn(0, OFF_W1, w1, (size_t)NEXP * HDIM * DDIM);
        cvOn(0, OFF_W3, w3, (size_t)NEXP * HDIM * DDIM);

        // side: W2 (needed by g2 on main), shared-expert conversions + SwiGLU
        cvOn(sS, OFF_W2, w2, (size_t)NEXP * DDIM * HDIM);
        cudaEventRecord(evW2, sS);
        cvOn(sS, OFF_SW1, sw1, (size_t)HSDIM * DDIM);
        cvOn(sS, OFF_SW3, sw3, (size_t)HSDIM * DDIM);
        cudaStreamWaitEvent(sS, evX, 0);
        g1_cp<false><<<dim3(HSDIM / 64, NTOK / 128, 1), 256, SMEM_G1, sS>>>(
            sb1, sb3, HSDIM, OFF_SW1, OFF_SW3, hHs);
        cvOn(sS, OFF_SW2, sw2, (size_t)DDIM * HSDIM);
        cudaEventRecord(evJoin, sS);

        // main: routed chain
        cudaStreamWaitEvent(0, evScan, 0);
        g1_cp<true><<<dim3(HDIM / 64, 64, NEXP), 256, SMEM_G1>>>(
            b1, b3, HDIM, OFF_W1, OFF_W3, hH);
        cudaStreamWaitEvent(0, evW2, 0);
        g2_cp<<<dim3(DDIM / 128, 64, NEXP), 256, SMEM_GG>>>(b2);

        // join + final
        cudaStreamWaitEvent(0, evJoin, 0);
        gf_cp<<<dim3(DDIM / 128, NTOK / 128), 256, SMEM_GG>>>(hHs, sb2, out);
    } else {
        // ---- fallback: proven sequential order (R16)
        cvOn(0, OFF_XR, x, (size_t)NTOK * DDIM);
        cvOn(0, OFF_W1, w1, (size_t)NEXP * HDIM * DDIM);
        cvOn(0, OFF_W3, w3, (size_t)NEXP * HDIM * DDIM);
        gate_kernel<<<NTOK / 8, 256>>>(x, gw, gb);
        scan_dispatch<<<NEXP, 256>>>();
        g1_cp<true><<<dim3(HDIM / 64, 64, NEXP), 256, SMEM_G1>>>(
            b1, b3, HDIM, OFF_W1, OFF_W3, hH);
        cvOn(0, OFF_W2, w2, (size_t)NEXP * DDIM * HDIM);
        g2_cp<<<dim3(DDIM / 128, 64, NEXP), 256, SMEM_GG>>>(b2);
        cvOn(0, OFF_SW1, sw1, (size_t)HSDIM * DDIM);
        cvOn(0, OFF_SW3, sw3, (size_t)HSDIM * DDIM);
        g1_cp<false><<<dim3(HSDIM / 64, NTOK / 128, 1), 256, SMEM_G1>>>(
            sb1, sb3, HSDIM, OFF_SW1, OFF_SW3, hHs);
        cvOn(0, OFF_SW2, sw2, (size_t)DDIM * HSDIM);
        gf_cp<<<dim3(DDIM / 128, NTOK / 128), 256, SMEM_GG>>>(hHs, sb2, out);
    }
}